// round 3
// baseline (speedup 1.0000x reference)
#include <cuda_runtime.h>
#include <math.h>

#define S_ 2048
#define D_ 768
#define H_ 12
#define DH_ 64
#define F_ 3072
#define L_ 2
#define W_ 256

// ---------------- scratch (static device memory; no allocations) -------------
__device__ float g_x[S_ * D_];        // residual stream
__device__ float g_qkv[3 * S_ * D_];  // q/k/v, each [s][h*64+dh]
__device__ float g_ctx[S_ * D_];      // attention output
__device__ float g_y[S_ * D_];        // pre-LN buffer
__device__ float g_h[S_ * F_];        // FFN hidden
__device__ int   g_pos[S_];           // position ids

// ---------------- block reductions -------------------------------------------
template <int NT>
__device__ __forceinline__ float blkSum(float v, float* red) {
    int tid = threadIdx.x;
    red[tid] = v; __syncthreads();
#pragma unroll
    for (int s = NT / 2; s > 0; s >>= 1) {
        if (tid < s) red[tid] += red[tid + s];
        __syncthreads();
    }
    float r = red[0]; __syncthreads();
    return r;
}

template <int NT>
__device__ __forceinline__ float blkMax(float v, float* red) {
    int tid = threadIdx.x;
    red[tid] = v; __syncthreads();
#pragma unroll
    for (int s = NT / 2; s > 0; s >>= 1) {
        if (tid < s) red[tid] = fmaxf(red[tid], red[tid + s]);
        __syncthreads();
    }
    float r = red[0]; __syncthreads();
    return r;
}

// ---------------- pos ids: cumsum(mask)*mask + 1 ------------------------------
__global__ void pos_kernel(const int* __restrict__ mask, int* __restrict__ pos) {
    __shared__ int part[257];
    int tid = threadIdx.x;          // 256 threads, 8 elems each
    int c[8];
    int acc = 0;
#pragma unroll
    for (int i = 0; i < 8; i++) {
        acc += mask[tid * 8 + i];
        c[i] = acc;
    }
    part[tid + 1] = acc;
    __syncthreads();
    if (tid == 0) {
        part[0] = 0;
        for (int i = 1; i <= 256; i++) part[i] += part[i - 1];
    }
    __syncthreads();
    int base = part[tid];
#pragma unroll
    for (int i = 0; i < 8; i++) {
        int idx = tid * 8 + i;
        pos[idx] = (base + c[i]) * mask[idx] + 1;
    }
}

// ---------------- embedding + LayerNorm --------------------------------------
__global__ void embed_ln_kernel(const int* __restrict__ ids, const int* __restrict__ pos,
                                const float* __restrict__ we, const float* __restrict__ pe,
                                const float* __restrict__ te,
                                const float* __restrict__ gs, const float* __restrict__ gb,
                                float* __restrict__ out) {
    int row = blockIdx.x;
    int tid = threadIdx.x;  // 256
    __shared__ float buf[D_];
    __shared__ float red[256];
    const float* w = we + (long)ids[row] * D_;
    const float* p = pe + (long)pos[row] * D_;
    float lsum = 0.f, lsq = 0.f;
#pragma unroll
    for (int i = 0; i < 3; i++) {
        int d = tid + i * 256;
        float v = w[d] + p[d] + te[d];
        buf[d] = v;
        lsum += v; lsq += v * v;
    }
    float total = blkSum<256>(lsum, red);
    float totsq = blkSum<256>(lsq, red);
    float mean = total * (1.f / D_);
    float var  = totsq * (1.f / D_) - mean * mean;
    float inv  = rsqrtf(var + 1e-5f);
#pragma unroll
    for (int i = 0; i < 3; i++) {
        int d = tid + i * 256;
        out[row * D_ + d] = (buf[d] - mean) * inv * gs[d] + gb[d];
    }
}

// ---------------- LayerNorm over a precomputed row ----------------------------
__global__ void ln_kernel(const float* __restrict__ in,
                          const float* __restrict__ gs, const float* __restrict__ gb,
                          float* __restrict__ out) {
    int row = blockIdx.x;
    int tid = threadIdx.x;  // 256
    __shared__ float red[256];
    const float* r = in + row * D_;
    float v0 = r[tid], v1 = r[tid + 256], v2 = r[tid + 512];
    float lsum = v0 + v1 + v2;
    float lsq = v0 * v0 + v1 * v1 + v2 * v2;
    float total = blkSum<256>(lsum, red);
    float totsq = blkSum<256>(lsq, red);
    float mean = total * (1.f / D_);
    float var  = totsq * (1.f / D_) - mean * mean;
    float inv  = rsqrtf(var + 1e-5f);
    out[row * D_ + tid]       = (v0 - mean) * inv * gs[tid]       + gb[tid];
    out[row * D_ + tid + 256] = (v1 - mean) * inv * gs[tid + 256] + gb[tid + 256];
    out[row * D_ + tid + 512] = (v2 - mean) * inv * gs[tid + 512] + gb[tid + 512];
}

// ---------------- 128x128x8 SGEMM, fused epilogue -----------------------------
// C[M,N] = act(A[M,K] @ B[K,N] + bias[N] (+ resid[M,N]))
// act: 0 = none, 1 = exact gelu
__global__ __launch_bounds__(256, 2)
void sgemm_kernel(const float* __restrict__ A, const float* __restrict__ B,
                  const float* __restrict__ bias, const float* __restrict__ resid,
                  float* __restrict__ C, int M, int N, int K, int act) {
    const int tid = threadIdx.x;
    const int tx = tid & 15;   // 0..15 (col groups)
    const int ty = tid >> 4;   // 0..15 (row groups)
    const int bRow = blockIdx.y * 128;
    const int bCol = blockIdx.x * 128;

    __shared__ float As[8][128];
    __shared__ float Bs[8][128];

    float acc[8][8];
#pragma unroll
    for (int i = 0; i < 8; i++)
#pragma unroll
        for (int j = 0; j < 8; j++) acc[i][j] = 0.f;

    const int arow = tid >> 1;
    const int ac   = (tid & 1) * 4;
    const int brow = tid >> 5;
    const int bc   = (tid & 31) * 4;

    for (int k0 = 0; k0 < K; k0 += 8) {
        float4 av = *(const float4*)(A + (long)(bRow + arow) * K + k0 + ac);
        float4 bv = *(const float4*)(B + (long)(k0 + brow) * N + bCol + bc);
        As[ac + 0][arow] = av.x;
        As[ac + 1][arow] = av.y;
        As[ac + 2][arow] = av.z;
        As[ac + 3][arow] = av.w;
        *(float4*)&Bs[brow][bc] = bv;
        __syncthreads();
#pragma unroll
        for (int kk = 0; kk < 8; kk++) {
            float a[8], b[8];
            *(float4*)(a)     = *(const float4*)&As[kk][ty * 4];
            *(float4*)(a + 4) = *(const float4*)&As[kk][64 + ty * 4];
            *(float4*)(b)     = *(const float4*)&Bs[kk][tx * 4];
            *(float4*)(b + 4) = *(const float4*)&Bs[kk][64 + tx * 4];
#pragma unroll
            for (int i = 0; i < 8; i++)
#pragma unroll
                for (int j = 0; j < 8; j++) acc[i][j] = fmaf(a[i], b[j], acc[i][j]);
        }
        __syncthreads();
    }

#pragma unroll
    for (int i = 0; i < 8; i++) {
        int r = bRow + ((i < 4) ? (ty * 4 + i) : (64 + ty * 4 + i - 4));
#pragma unroll
        for (int j = 0; j < 8; j++) {
            int c = bCol + ((j < 4) ? (tx * 4 + j) : (64 + tx * 4 + j - 4));
            float v = acc[i][j] + bias[c];
            if (resid) v += resid[(long)r * N + c];
            if (act == 1) v = 0.5f * v * (1.0f + erff(v * 0.70710678118654752f));
            C[(long)r * N + c] = v;
        }
    }
}

// ---------------- banded attention: one block per (query, head) ---------------
__global__ void attn_kernel(const float* __restrict__ qkv, const int* __restrict__ mask,
                            float* __restrict__ ctx) {
    const int q = blockIdx.x;
    const int h = blockIdx.y;
    const int tid = threadIdx.x;  // 128

    __shared__ float qv[DH_];
    __shared__ float sc[2 * W_ + 1];
    __shared__ float red[128];

    const float* Kbase = qkv + 1 * S_ * D_;
    const float* Vbase = qkv + 2 * S_ * D_;

    if (tid < DH_) qv[tid] = qkv[(long)q * D_ + h * DH_ + tid];

    const int j0 = max(0, q - W_);
    const int j1 = min(S_ - 1, q + W_);
    const int nk = j1 - j0 + 1;
    __syncthreads();

    // scores
    for (int jj = tid; jj < nk; jj += 128) {
        int j = j0 + jj;
        float s;
        if (mask[j]) {
            const float4* kv4 = (const float4*)(Kbase + (long)j * D_ + h * DH_);
            float acc = 0.f;
#pragma unroll
            for (int d4 = 0; d4 < 16; d4++) {
                float4 kk = kv4[d4];
                acc += qv[d4 * 4 + 0] * kk.x + qv[d4 * 4 + 1] * kk.y +
                       qv[d4 * 4 + 2] * kk.z + qv[d4 * 4 + 3] * kk.w;
            }
            s = acc * 0.125f;  // 1/sqrt(64)
        } else {
            s = -1e9f;
        }
        sc[jj] = s;
    }
    __syncthreads();

    // softmax
    float lm = -3.4e38f;
    for (int jj = tid; jj < nk; jj += 128) lm = fmaxf(lm, sc[jj]);
    float m = blkMax<128>(lm, red);
    float lsum = 0.f;
    for (int jj = tid; jj < nk; jj += 128) {
        float e = __expf(sc[jj] - m);
        sc[jj] = e;
        lsum += e;
    }
    float denom = blkSum<128>(lsum, red);
    float invd = 1.0f / denom;
    __syncthreads();

    // ctx: 2 threads per dim
    const int d = tid & 63;
    const int half = tid >> 6;
    float acc = 0.f;
    for (int jj = half; jj < nk; jj += 2) {
        acc += sc[jj] * Vbase[(long)(j0 + jj) * D_ + h * DH_ + d];
    }
    red[tid] = acc;
    __syncthreads();
    if (tid < 64) {
        ctx[(long)q * D_ + h * DH_ + tid] = (red[tid] + red[tid + 64]) * invd;
    }
}

// ---------------- pooled head: tanh(x[0] @ W + b) -----------------------------
__global__ void pool_kernel(const float* __restrict__ x, const float* __restrict__ Wp,
                            const float* __restrict__ bp, float* __restrict__ out) {
    __shared__ float x0[D_];
    int tid = threadIdx.x;  // 128
    for (int i = tid; i < D_; i += 128) x0[i] = x[i];
    __syncthreads();
    int e = blockIdx.x * 128 + tid;
    float acc = bp[e];
    for (int d = 0; d < D_; d++) acc = fmaf(x0[d], Wp[(long)d * D_ + e], acc);
    out[e] = tanhf(acc);
}

__global__ void copy_kernel(const float* __restrict__ in, float* __restrict__ out, int n) {
    int i = blockIdx.x * blockDim.x + threadIdx.x;
    if (i < n) out[i] = in[i];
}

// ---------------- launch -------------------------------------------------------
extern "C" void kernel_launch(void* const* d_in, const int* in_sizes, int n_in,
                              void* d_out, int out_size) {
    const int*   input_ids = (const int*)d_in[0];
    const int*   attn_mask = (const int*)d_in[1];
    const float* word_emb  = (const float*)d_in[2];
    const float* pos_emb   = (const float*)d_in[3];
    const float* type_emb  = (const float*)d_in[4];
    const float* emb_ln_s  = (const float*)d_in[5];
    const float* emb_ln_b  = (const float*)d_in[6];
    const float* Wqkv      = (const float*)d_in[7];
    const float* bqkv      = (const float*)d_in[8];
    const float* Wo        = (const float*)d_in[9];
    const float* bo        = (const float*)d_in[10];
    const float* ln1_s     = (const float*)d_in[11];
    const float* ln1_b     = (const float*)d_in[12];
    const float* W1        = (const float*)d_in[13];
    const float* b1        = (const float*)d_in[14];
    const float* W2        = (const float*)d_in[15];
    const float* b2        = (const float*)d_in[16];
    const float* ln2_s     = (const float*)d_in[17];
    const float* ln2_b     = (const float*)d_in[18];
    const float* pool_W    = (const float*)d_in[19];
    const float* pool_b    = (const float*)d_in[20];
    float* out = (float*)d_out;

    float *x, *qkv, *ctx, *y, *hbuf;
    int* pos;
    cudaGetSymbolAddress((void**)&x, g_x);
    cudaGetSymbolAddress((void**)&qkv, g_qkv);
    cudaGetSymbolAddress((void**)&ctx, g_ctx);
    cudaGetSymbolAddress((void**)&y, g_y);
    cudaGetSymbolAddress((void**)&hbuf, g_h);
    cudaGetSymbolAddress((void**)&pos, g_pos);

    pos_kernel<<<1, 256>>>(attn_mask, pos);
    embed_ln_kernel<<<S_, 256>>>(input_ids, pos, word_emb, pos_emb, type_emb,
                                 emb_ln_s, emb_ln_b, x);

    for (int l = 0; l < L_; l++) {
        // QKV projections
        for (int t = 0; t < 3; t++) {
            sgemm_kernel<<<dim3(D_ / 128, S_ / 128), 256>>>(
                x, Wqkv + (long)(l * 3 + t) * D_ * D_,
                bqkv + (long)(l * 3 + t) * D_, nullptr,
                qkv + (long)t * S_ * D_, S_, D_, D_, 0);
        }
        // banded attention
        attn_kernel<<<dim3(S_, H_), 128>>>(qkv, attn_mask, ctx);
        // output projection + residual, then LN
        sgemm_kernel<<<dim3(D_ / 128, S_ / 128), 256>>>(
            ctx, Wo + (long)l * D_ * D_, bo + (long)l * D_, x, y, S_, D_, D_, 0);
        ln_kernel<<<S_, 256>>>(y, ln1_s + (long)l * D_, ln1_b + (long)l * D_, x);
        // FFN
        sgemm_kernel<<<dim3(F_ / 128, S_ / 128), 256>>>(
            x, W1 + (long)l * D_ * F_, b1 + (long)l * F_, nullptr, hbuf, S_, F_, D_, 1);
        sgemm_kernel<<<dim3(D_ / 128, S_ / 128), 256>>>(
            hbuf, W2 + (long)l * F_ * D_, b2 + (long)l * D_, x, y, S_, D_, F_, 0);
        ln_kernel<<<S_, 256>>>(y, ln2_s + (long)l * D_, ln2_b + (long)l * D_, x);
    }

    copy_kernel<<<(S_ * D_ + 255) / 256, 256>>>(x, out, S_ * D_);
    pool_kernel<<<D_ / 128, 128>>>(x, pool_W, pool_b, out + (long)S_ * D_);
}

// round 5
// speedup vs baseline: 1.0009x; 1.0009x over previous
#include <cuda_runtime.h>
#include <math.h>

#define S_ 2048
#define D_ 768
#define H_ 12
#define DH_ 64
#define F_ 3072
#define L_ 2
#define W_ 256

// ---------------- scratch (static device memory; no allocations) -------------
__device__ float g_x[S_ * D_];        // residual stream
__device__ float g_qkv[3 * S_ * D_];  // q/k/v, each [s][h*64+dh]
__device__ float g_ctx[S_ * D_];      // attention output
__device__ float g_y[S_ * D_];        // pre-LN buffer
__device__ float g_h[S_ * F_];        // FFN hidden
__device__ int   g_pos[S_];           // position ids

// ---------------- block reductions -------------------------------------------
template <int NT>
__device__ __forceinline__ float blkSum(float v, float* red) {
    int tid = threadIdx.x;
    red[tid] = v; __syncthreads();
#pragma unroll
    for (int s = NT / 2; s > 0; s >>= 1) {
        if (tid < s) red[tid] += red[tid + s];
        __syncthreads();
    }
    float r = red[0]; __syncthreads();
    return r;
}

template <int NT>
__device__ __forceinline__ float blkMax(float v, float* red) {
    int tid = threadIdx.x;
    red[tid] = v; __syncthreads();
#pragma unroll
    for (int s = NT / 2; s > 0; s >>= 1) {
        if (tid < s) red[tid] = fmaxf(red[tid], red[tid + s]);
        __syncthreads();
    }
    float r = red[0]; __syncthreads();
    return r;
}

// ---------------- pos ids: cumsum(mask)*mask + 1 ------------------------------
__global__ void pos_kernel(const int* __restrict__ mask, int* __restrict__ pos) {
    __shared__ int part[257];
    int tid = threadIdx.x;          // 256 threads, 8 elems each
    int c[8];
    int acc = 0;
#pragma unroll
    for (int i = 0; i < 8; i++) {
        acc += mask[tid * 8 + i];
        c[i] = acc;
    }
    part[tid + 1] = acc;
    __syncthreads();
    if (tid == 0) {
        part[0] = 0;
        for (int i = 1; i <= 256; i++) part[i] += part[i - 1];
    }
    __syncthreads();
    int base = part[tid];
#pragma unroll
    for (int i = 0; i < 8; i++) {
        int idx = tid * 8 + i;
        pos[idx] = (base + c[i]) * mask[idx] + 1;
    }
}

// ---------------- embedding + LayerNorm --------------------------------------
__global__ void embed_ln_kernel(const int* __restrict__ ids, const int* __restrict__ pos,
                                const float* __restrict__ we, const float* __restrict__ pe,
                                const float* __restrict__ te,
                                const float* __restrict__ gs, const float* __restrict__ gb,
                                float* __restrict__ out) {
    int row = blockIdx.x;
    int tid = threadIdx.x;  // 256
    __shared__ float buf[D_];
    __shared__ float red[256];
    const float* w = we + (long)ids[row] * D_;
    const float* p = pe + (long)pos[row] * D_;
    float lsum = 0.f, lsq = 0.f;
#pragma unroll
    for (int i = 0; i < 3; i++) {
        int d = tid + i * 256;
        float v = w[d] + p[d] + te[d];
        buf[d] = v;
        lsum += v; lsq += v * v;
    }
    float total = blkSum<256>(lsum, red);
    float totsq = blkSum<256>(lsq, red);
    float mean = total * (1.f / D_);
    float var  = totsq * (1.f / D_) - mean * mean;
    float inv  = rsqrtf(var + 1e-5f);
#pragma unroll
    for (int i = 0; i < 3; i++) {
        int d = tid + i * 256;
        out[row * D_ + d] = (buf[d] - mean) * inv * gs[d] + gb[d];
    }
}

// ---------------- LayerNorm over a precomputed row ----------------------------
__global__ void ln_kernel(const float* __restrict__ in,
                          const float* __restrict__ gs, const float* __restrict__ gb,
                          float* __restrict__ out) {
    int row = blockIdx.x;
    int tid = threadIdx.x;  // 256
    __shared__ float red[256];
    const float* r = in + row * D_;
    float v0 = r[tid], v1 = r[tid + 256], v2 = r[tid + 512];
    float lsum = v0 + v1 + v2;
    float lsq = v0 * v0 + v1 * v1 + v2 * v2;
    float total = blkSum<256>(lsum, red);
    float totsq = blkSum<256>(lsq, red);
    float mean = total * (1.f / D_);
    float var  = totsq * (1.f / D_) - mean * mean;
    float inv  = rsqrtf(var + 1e-5f);
    out[row * D_ + tid]       = (v0 - mean) * inv * gs[tid]       + gb[tid];
    out[row * D_ + tid + 256] = (v1 - mean) * inv * gs[tid + 256] + gb[tid + 256];
    out[row * D_ + tid + 512] = (v2 - mean) * inv * gs[tid + 512] + gb[tid + 512];
}

// ---------------- 128x128x8 SGEMM, fused epilogue -----------------------------
// C[M,N] = act(A[M,K] @ B[K,N] + bias[N] (+ resid[M,N]))
// act: 0 = none, 1 = exact gelu
__global__ __launch_bounds__(256, 2)
void sgemm_kernel(const float* __restrict__ A, const float* __restrict__ B,
                  const float* __restrict__ bias, const float* __restrict__ resid,
                  float* __restrict__ C, int M, int N, int K, int act) {
    const int tid = threadIdx.x;
    const int tx = tid & 15;   // 0..15 (col groups)
    const int ty = tid >> 4;   // 0..15 (row groups)
    const int bRow = blockIdx.y * 128;
    const int bCol = blockIdx.x * 128;

    __shared__ float As[8][128];
    __shared__ float Bs[8][128];

    float acc[8][8];
#pragma unroll
    for (int i = 0; i < 8; i++)
#pragma unroll
        for (int j = 0; j < 8; j++) acc[i][j] = 0.f;

    const int arow = tid >> 1;
    const int ac   = (tid & 1) * 4;
    const int brow = tid >> 5;
    const int bc   = (tid & 31) * 4;

    for (int k0 = 0; k0 < K; k0 += 8) {
        float4 av = *(const float4*)(A + (long)(bRow + arow) * K + k0 + ac);
        float4 bv = *(const float4*)(B + (long)(k0 + brow) * N + bCol + bc);
        As[ac + 0][arow] = av.x;
        As[ac + 1][arow] = av.y;
        As[ac + 2][arow] = av.z;
        As[ac + 3][arow] = av.w;
        *(float4*)&Bs[brow][bc] = bv;
        __syncthreads();
#pragma unroll
        for (int kk = 0; kk < 8; kk++) {
            float a[8], b[8];
            *(float4*)(a)     = *(const float4*)&As[kk][ty * 4];
            *(float4*)(a + 4) = *(const float4*)&As[kk][64 + ty * 4];
            *(float4*)(b)     = *(const float4*)&Bs[kk][tx * 4];
            *(float4*)(b + 4) = *(const float4*)&Bs[kk][64 + tx * 4];
#pragma unroll
            for (int i = 0; i < 8; i++)
#pragma unroll
                for (int j = 0; j < 8; j++) acc[i][j] = fmaf(a[i], b[j], acc[i][j]);
        }
        __syncthreads();
    }

#pragma unroll
    for (int i = 0; i < 8; i++) {
        int r = bRow + ((i < 4) ? (ty * 4 + i) : (64 + ty * 4 + i - 4));
#pragma unroll
        for (int j = 0; j < 8; j++) {
            int c = bCol + ((j < 4) ? (tx * 4 + j) : (64 + tx * 4 + j - 4));
            float v = acc[i][j] + bias[c];
            if (resid) v += resid[(long)r * N + c];
            if (act == 1) v = 0.5f * v * (1.0f + erff(v * 0.70710678118654752f));
            C[(long)r * N + c] = v;
        }
    }
}

// ---------------- banded attention: one block per (query, head) ---------------
__global__ void attn_kernel(const float* __restrict__ qkv, const int* __restrict__ mask,
                            float* __restrict__ ctx) {
    const int q = blockIdx.x;
    const int h = blockIdx.y;
    const int tid = threadIdx.x;  // 128

    __shared__ float qv[DH_];
    __shared__ float sc[2 * W_ + 1];
    __shared__ float red[128];

    const float* Kbase = qkv + 1 * S_ * D_;
    const float* Vbase = qkv + 2 * S_ * D_;

    if (tid < DH_) qv[tid] = qkv[(long)q * D_ + h * DH_ + tid];

    const int j0 = max(0, q - W_);
    const int j1 = min(S_ - 1, q + W_);
    const int nk = j1 - j0 + 1;
    __syncthreads();

    // scores
    for (int jj = tid; jj < nk; jj += 128) {
        int j = j0 + jj;
        float s;
        if (mask[j]) {
            const float4* kv4 = (const float4*)(Kbase + (long)j * D_ + h * DH_);
            float acc = 0.f;
#pragma unroll
            for (int d4 = 0; d4 < 16; d4++) {
                float4 kk = kv4[d4];
                acc += qv[d4 * 4 + 0] * kk.x + qv[d4 * 4 + 1] * kk.y +
                       qv[d4 * 4 + 2] * kk.z + qv[d4 * 4 + 3] * kk.w;
            }
            s = acc * 0.125f;  // 1/sqrt(64)
        } else {
            s = -1e9f;
        }
        sc[jj] = s;
    }
    __syncthreads();

    // softmax
    float lm = -3.4e38f;
    for (int jj = tid; jj < nk; jj += 128) lm = fmaxf(lm, sc[jj]);
    float m = blkMax<128>(lm, red);
    float lsum = 0.f;
    for (int jj = tid; jj < nk; jj += 128) {
        float e = __expf(sc[jj] - m);
        sc[jj] = e;
        lsum += e;
    }
    float denom = blkSum<128>(lsum, red);
    float invd = 1.0f / denom;
    __syncthreads();

    // ctx: 2 threads per dim
    const int d = tid & 63;
    const int half = tid >> 6;
    float acc = 0.f;
    for (int jj = half; jj < nk; jj += 2) {
        acc += sc[jj] * Vbase[(long)(j0 + jj) * D_ + h * DH_ + d];
    }
    red[tid] = acc;
    __syncthreads();
    if (tid < 64) {
        ctx[(long)q * D_ + h * DH_ + tid] = (red[tid] + red[tid + 64]) * invd;
    }
}

// ---------------- pooled head: tanh(x[0] @ W + b) -----------------------------
__global__ void pool_kernel(const float* __restrict__ x, const float* __restrict__ Wp,
                            const float* __restrict__ bp, float* __restrict__ out) {
    __shared__ float x0[D_];
    int tid = threadIdx.x;  // 128
    for (int i = tid; i < D_; i += 128) x0[i] = x[i];
    __syncthreads();
    int e = blockIdx.x * 128 + tid;
    float acc = bp[e];
    for (int d = 0; d < D_; d++) acc = fmaf(x0[d], Wp[(long)d * D_ + e], acc);
    out[e] = tanhf(acc);
}

__global__ void copy_kernel(const float* __restrict__ in, float* __restrict__ out, int n) {
    int i = blockIdx.x * blockDim.x + threadIdx.x;
    if (i < n) out[i] = in[i];
}

// ---------------- launch -------------------------------------------------------
extern "C" void kernel_launch(void* const* d_in, const int* in_sizes, int n_in,
                              void* d_out, int out_size) {
    const int*   input_ids = (const int*)d_in[0];
    const int*   attn_mask = (const int*)d_in[1];
    const float* word_emb  = (const float*)d_in[2];
    const float* pos_emb   = (const float*)d_in[3];
    const float* type_emb  = (const float*)d_in[4];
    const float* emb_ln_s  = (const float*)d_in[5];
    const float* emb_ln_b  = (const float*)d_in[6];
    const float* Wqkv      = (const float*)d_in[7];
    const float* bqkv      = (const float*)d_in[8];
    const float* Wo        = (const float*)d_in[9];
    const float* bo        = (const float*)d_in[10];
    const float* ln1_s     = (const float*)d_in[11];
    const float* ln1_b     = (const float*)d_in[12];
    const float* W1        = (const float*)d_in[13];
    const float* b1        = (const float*)d_in[14];
    const float* W2        = (const float*)d_in[15];
    const float* b2        = (const float*)d_in[16];
    const float* ln2_s     = (const float*)d_in[17];
    const float* ln2_b     = (const float*)d_in[18];
    const float* pool_W    = (const float*)d_in[19];
    const float* pool_b    = (const float*)d_in[20];
    float* out = (float*)d_out;

    float *x, *qkv, *ctx, *y, *hbuf;
    int* pos;
    cudaGetSymbolAddress((void**)&x, g_x);
    cudaGetSymbolAddress((void**)&qkv, g_qkv);
    cudaGetSymbolAddress((void**)&ctx, g_ctx);
    cudaGetSymbolAddress((void**)&y, g_y);
    cudaGetSymbolAddress((void**)&hbuf, g_h);
    cudaGetSymbolAddress((void**)&pos, g_pos);

    pos_kernel<<<1, 256>>>(attn_mask, pos);
    embed_ln_kernel<<<S_, 256>>>(input_ids, pos, word_emb, pos_emb, type_emb,
                                 emb_ln_s, emb_ln_b, x);

    for (int l = 0; l < L_; l++) {
        // QKV projections
        for (int t = 0; t < 3; t++) {
            sgemm_kernel<<<dim3(D_ / 128, S_ / 128), 256>>>(
                x, Wqkv + (long)(l * 3 + t) * D_ * D_,
                bqkv + (long)(l * 3 + t) * D_, nullptr,
                qkv + (long)t * S_ * D_, S_, D_, D_, 0);
        }
        // banded attention
        attn_kernel<<<dim3(S_, H_), 128>>>(qkv, attn_mask, ctx);
        // output projection + residual, then LN
        sgemm_kernel<<<dim3(D_ / 128, S_ / 128), 256>>>(
            ctx, Wo + (long)l * D_ * D_, bo + (long)l * D_, x, y, S_, D_, D_, 0);
        ln_kernel<<<S_, 256>>>(y, ln1_s + (long)l * D_, ln1_b + (long)l * D_, x);
        // FFN
        sgemm_kernel<<<dim3(F_ / 128, S_ / 128), 256>>>(
            x, W1 + (long)l * D_ * F_, b1 + (long)l * F_, nullptr, hbuf, S_, F_, D_, 1);
        sgemm_kernel<<<dim3(D_ / 128, S_ / 128), 256>>>(
            hbuf, W2 + (long)l * F_ * D_, b2 + (long)l * D_, x, y, S_, D_, F_, 0);
        ln_kernel<<<S_, 256>>>(y, ln2_s + (long)l * D_, ln2_b + (long)l * D_, x);
    }

    copy_kernel<<<(S_ * D_ + 255) / 256, 256>>>(x, out, S_ * D_);
    pool_kernel<<<D_ / 128, 128>>>(x, pool_W, pool_b, out + (long)S_ * D_);
}

// round 8
// speedup vs baseline: 1.1205x; 1.1196x over previous
#include <cuda_runtime.h>
#include <math.h>
#include <mma.h>

using namespace nvcuda;

#define S_ 2048
#define D_ 768
#define H_ 12
#define DH_ 64
#define F_ 3072
#define L_ 2
#define W_ 256
#define SCW 520   // padded 2W+1=513 score-row stride

// ---------------- scratch (static device memory; no allocations) -------------
__device__ float g_x[S_ * D_];        // residual stream
__device__ float g_qkv[3 * S_ * D_];  // q/k/v, each [s][h*64+dh]
__device__ float g_ctx[S_ * D_];      // attention output
__device__ float g_y[S_ * D_];        // pre-LN buffer
__device__ float g_h[S_ * F_];        // FFN hidden
__device__ float g_sc[H_ * S_ * SCW]; // banded attention scores/probs
__device__ int   g_pos[S_];           // position ids

// ---------------- block reductions -------------------------------------------
template <int NT>
__device__ __forceinline__ float blkSum(float v, float* red) {
    int tid = threadIdx.x;
    red[tid] = v; __syncthreads();
#pragma unroll
    for (int s = NT / 2; s > 0; s >>= 1) {
        if (tid < s) red[tid] += red[tid + s];
        __syncthreads();
    }
    float r = red[0]; __syncthreads();
    return r;
}

template <int NT>
__device__ __forceinline__ float blkMax(float v, float* red) {
    int tid = threadIdx.x;
    red[tid] = v; __syncthreads();
#pragma unroll
    for (int s = NT / 2; s > 0; s >>= 1) {
        if (tid < s) red[tid] = fmaxf(red[tid], red[tid + s]);
        __syncthreads();
    }
    float r = red[0]; __syncthreads();
    return r;
}

// ---------------- pos ids: cumsum(mask)*mask + 1 ------------------------------
__global__ void pos_kernel(const int* __restrict__ mask, int* __restrict__ pos) {
    __shared__ int part[257];
    int tid = threadIdx.x;          // 256 threads, 8 elems each
    int c[8];
    int acc = 0;
#pragma unroll
    for (int i = 0; i < 8; i++) {
        acc += mask[tid * 8 + i];
        c[i] = acc;
    }
    part[tid + 1] = acc;
    __syncthreads();
    if (tid == 0) {
        part[0] = 0;
        for (int i = 1; i <= 256; i++) part[i] += part[i - 1];
    }
    __syncthreads();
    int base = part[tid];
#pragma unroll
    for (int i = 0; i < 8; i++) {
        int idx = tid * 8 + i;
        pos[idx] = (base + c[i]) * mask[idx] + 1;
    }
}

// ---------------- embedding + LayerNorm --------------------------------------
__global__ void embed_ln_kernel(const int* __restrict__ ids, const int* __restrict__ pos,
                                const float* __restrict__ we, const float* __restrict__ pe,
                                const float* __restrict__ te,
                                const float* __restrict__ gs, const float* __restrict__ gb,
                                float* __restrict__ out) {
    int row = blockIdx.x;
    int tid = threadIdx.x;  // 256
    __shared__ float buf[D_];
    __shared__ float red[256];
    const float* w = we + (long)ids[row] * D_;
    const float* p = pe + (long)pos[row] * D_;
    float lsum = 0.f, lsq = 0.f;
#pragma unroll
    for (int i = 0; i < 3; i++) {
        int d = tid + i * 256;
        float v = w[d] + p[d] + te[d];
        buf[d] = v;
        lsum += v; lsq += v * v;
    }
    float total = blkSum<256>(lsum, red);
    float totsq = blkSum<256>(lsq, red);
    float mean = total * (1.f / D_);
    float var  = totsq * (1.f / D_) - mean * mean;
    float inv  = rsqrtf(var + 1e-5f);
#pragma unroll
    for (int i = 0; i < 3; i++) {
        int d = tid + i * 256;
        out[row * D_ + d] = (buf[d] - mean) * inv * gs[d] + gb[d];
    }
}

// ---------------- LayerNorm over a precomputed row ----------------------------
__global__ void ln_kernel(const float* __restrict__ in,
                          const float* __restrict__ gs, const float* __restrict__ gb,
                          float* __restrict__ out) {
    int row = blockIdx.x;
    int tid = threadIdx.x;  // 256
    __shared__ float red[256];
    const float* r = in + row * D_;
    float v0 = r[tid], v1 = r[tid + 256], v2 = r[tid + 512];
    float lsum = v0 + v1 + v2;
    float lsq = v0 * v0 + v1 * v1 + v2 * v2;
    float total = blkSum<256>(lsum, red);
    float totsq = blkSum<256>(lsq, red);
    float mean = total * (1.f / D_);
    float var  = totsq * (1.f / D_) - mean * mean;
    float inv  = rsqrtf(var + 1e-5f);
    out[row * D_ + tid]       = (v0 - mean) * inv * gs[tid]       + gb[tid];
    out[row * D_ + tid + 256] = (v1 - mean) * inv * gs[tid + 256] + gb[tid + 256];
    out[row * D_ + tid + 512] = (v2 - mean) * inv * gs[tid + 512] + gb[tid + 512];
}

// ---------------- TF32 tensor-core GEMM (3xTF32, fp32 accuracy) ---------------
// C[M,N] = act(A[M,K] @ B[K,N] + bias[N] (+ resid[M,N]))
// Block tile 128x64, BK=16, 8 warps with 32x32 warp tiles.
#define BM 128
#define BN 64
#define BK 16
#define LDA (BK + 8)   // 24
#define LDB (BN + 8)   // 72

__device__ __forceinline__ float f2tf32(float x) {
    float r;
    asm("cvt.rna.tf32.f32 %0, %1;" : "=f"(r) : "f"(x));
    return r;
}

__global__ __launch_bounds__(256, 2)
void tgemm_kernel(const float* __restrict__ A, const float* __restrict__ B,
                  const float* __restrict__ bias, const float* __restrict__ resid,
                  float* __restrict__ C, int M, int N, int K, int act) {
    __shared__ float sbuf[2 * BM * LDA + 2 * BK * LDB];  // 33792 bytes
    float (*As_hi)[LDA] = (float(*)[LDA])(sbuf);
    float (*As_lo)[LDA] = (float(*)[LDA])(sbuf + BM * LDA);
    float (*Bs_hi)[LDB] = (float(*)[LDB])(sbuf + 2 * BM * LDA);
    float (*Bs_lo)[LDB] = (float(*)[LDB])(sbuf + 2 * BM * LDA + BK * LDB);

    const int tid = threadIdx.x;
    const int lane = tid & 31;
    const int wid = tid >> 5;          // 0..7
    const int wr = wid >> 1;           // 0..3 -> rows
    const int wc = wid & 1;            // 0..1 -> cols
    const int bRow = blockIdx.y * BM;
    const int bCol = blockIdx.x * BN;

    // gmem load mapping
    const int ar  = tid >> 2;          // 0..63 (rows ar, ar+64)
    const int ac4 = (tid & 3) * 4;     // 0,4,8,12
    const int br  = tid >> 4;          // 0..15
    const int bc4 = (tid & 15) * 4;    // 0..60

    const float* Ap  = A + (long)(bRow + ar) * K + ac4;
    const float* Ap2 = Ap + 64l * K;
    const float* Bp  = B + (long)br * N + bCol + bc4;

    wmma::fragment<wmma::accumulator, 16, 16, 8, float> acc[2][2];
#pragma unroll
    for (int i = 0; i < 2; i++)
#pragma unroll
        for (int j = 0; j < 2; j++) wmma::fill_fragment(acc[i][j], 0.0f);

    float4 ra0 = *(const float4*)(Ap);
    float4 ra1 = *(const float4*)(Ap2);
    float4 rb  = *(const float4*)(Bp);

    for (int k0 = 0; k0 < K; k0 += BK) {
        // store staged regs -> smem with hi/lo tf32 split
        {
            float va[4] = {ra0.x, ra0.y, ra0.z, ra0.w};
            float vb[4] = {ra1.x, ra1.y, ra1.z, ra1.w};
            float vc[4] = {rb.x, rb.y, rb.z, rb.w};
#pragma unroll
            for (int e = 0; e < 4; e++) {
                float v = va[e], hi = f2tf32(v);
                As_hi[ar][ac4 + e] = hi;
                As_lo[ar][ac4 + e] = f2tf32(v - hi);
            }
#pragma unroll
            for (int e = 0; e < 4; e++) {
                float v = vb[e], hi = f2tf32(v);
                As_hi[ar + 64][ac4 + e] = hi;
                As_lo[ar + 64][ac4 + e] = f2tf32(v - hi);
            }
#pragma unroll
            for (int e = 0; e < 4; e++) {
                float v = vc[e], hi = f2tf32(v);
                Bs_hi[br][bc4 + e] = hi;
                Bs_lo[br][bc4 + e] = f2tf32(v - hi);
            }
        }
        __syncthreads();

        // prefetch next k-tile into registers (hides gmem latency behind mma)
        if (k0 + BK < K) {
            ra0 = *(const float4*)(Ap + k0 + BK);
            ra1 = *(const float4*)(Ap2 + k0 + BK);
            rb  = *(const float4*)(Bp + (long)(k0 + BK) * N);
        }

#pragma unroll
        for (int ks = 0; ks < BK; ks += 8) {
            wmma::fragment<wmma::matrix_a, 16, 16, 8, wmma::precision::tf32, wmma::row_major> a_hi[2], a_lo[2];
            wmma::fragment<wmma::matrix_b, 16, 16, 8, wmma::precision::tf32, wmma::row_major> b_hi[2], b_lo[2];
#pragma unroll
            for (int i = 0; i < 2; i++) {
                wmma::load_matrix_sync(a_hi[i], &As_hi[wr * 32 + i * 16][ks], LDA);
                wmma::load_matrix_sync(a_lo[i], &As_lo[wr * 32 + i * 16][ks], LDA);
            }
#pragma unroll
            for (int j = 0; j < 2; j++) {
                wmma::load_matrix_sync(b_hi[j], &Bs_hi[ks][wc * 32 + j * 16], LDB);
                wmma::load_matrix_sync(b_lo[j], &Bs_lo[ks][wc * 32 + j * 16], LDB);
            }
#pragma unroll
            for (int i = 0; i < 2; i++)
#pragma unroll
                for (int j = 0; j < 2; j++) {
                    wmma::mma_sync(acc[i][j], a_lo[i], b_hi[j], acc[i][j]);
                    wmma::mma_sync(acc[i][j], a_hi[i], b_lo[j], acc[i][j]);
                    wmma::mma_sync(acc[i][j], a_hi[i], b_hi[j], acc[i][j]);
                }
        }
        __syncthreads();
    }

    // epilogue: per-warp staging through smem (no cross-warp sync needed)
    float* ws = sbuf + wid * (16 * 36);
#pragma unroll
    for (int mi = 0; mi < 2; mi++) {
        wmma::store_matrix_sync(ws,      acc[mi][0], 36, wmma::mem_row_major);
        wmma::store_matrix_sync(ws + 16, acc[mi][1], 36, wmma::mem_row_major);
        __syncwarp();
#pragma unroll
        for (int r = 0; r < 16; r++) {
            int gr = bRow + wr * 32 + mi * 16 + r;
            int gc = bCol + wc * 32 + lane;
            float v = ws[r * 36 + lane] + bias[gc];
            if (resid) v += resid[(long)gr * N + gc];
            if (act == 1) v = 0.5f * v * (1.0f + erff(v * 0.70710678118654752f));
            C[(long)gr * N + gc] = v;
        }
        __syncwarp();
    }
}

// ---------------- banded attention, phase 1: scores ---------------------------
// grid (S/64, H), block 256. Q tile (64x64) + K chunks (64x64) in smem.
__global__ void attn_scores_kernel(const float* __restrict__ qkv, const int* __restrict__ mask,
                                   float* __restrict__ sc) {
    const int q0 = blockIdx.x * 64;
    const int h  = blockIdx.y;
    const int tid = threadIdx.x;  // 256
    __shared__ float Qs[64][65];
    __shared__ float Ks[64][65];
    __shared__ int   sm[64];
    const float* Kb = qkv + (long)S_ * D_;

    for (int idx = tid; idx < 4096; idx += 256) {
        int r = idx >> 6, c = idx & 63;
        Qs[r][c] = qkv[(long)(q0 + r) * D_ + h * DH_ + c] * 0.125f;  // fold 1/sqrt(64)
    }

    const int qg = tid >> 4;   // 0..15 (4 q rows each)
    const int kg = tid & 15;   // 0..15 (4 k cols each)

    for (int ch = 0; ch < 9; ch++) {
        int jb = q0 - W_ + ch * 64;
        __syncthreads();  // protect Qs (first iter) / Ks,sm (later iters)
        for (int idx = tid; idx < 4096; idx += 256) {
            int r = idx >> 6, c = idx & 63;
            int j = jb + r;
            Ks[r][c] = (j >= 0 && j < S_) ? Kb[(long)j * D_ + h * DH_ + c] : 0.f;
        }
        if (tid < 64) {
            int j = jb + tid;
            sm[tid] = (j >= 0 && j < S_) ? mask[j] : 0;
        }
        __syncthreads();

        float accs[4][4];
#pragma unroll
        for (int i = 0; i < 4; i++)
#pragma unroll
            for (int j = 0; j < 4; j++) accs[i][j] = 0.f;

#pragma unroll 8
        for (int d = 0; d < 64; d++) {
            float qv[4], kv[4];
#pragma unroll
            for (int i = 0; i < 4; i++) qv[i] = Qs[qg * 4 + i][d];
#pragma unroll
            for (int j = 0; j < 4; j++) kv[j] = Ks[kg * 4 + j][d];
#pragma unroll
            for (int i = 0; i < 4; i++)
#pragma unroll
                for (int j = 0; j < 4; j++) accs[i][j] = fmaf(qv[i], kv[j], accs[i][j]);
        }

#pragma unroll
        for (int i = 0; i < 4; i++) {
            int q = q0 + qg * 4 + i;
#pragma unroll
            for (int j = 0; j < 4; j++) {
                int jg = jb + kg * 4 + j;
                int jj = jg - q + W_;
                if (jj >= 0 && jj <= 2 * W_) {
                    float v = sm[kg * 4 + j] ? accs[i][j] : -1e9f;
                    sc[((long)h * S_ + q) * SCW + jj] = v;
                }
            }
        }
    }
}

// ---------------- phase 2: rowwise softmax over the 513-band ------------------
__global__ void attn_softmax_kernel(float* __restrict__ sc) {
    const int q = blockIdx.x;
    const int h = blockIdx.y;
    const int tid = threadIdx.x;  // 128
    __shared__ float red[128];
    float* row = sc + ((long)h * S_ + q) * SCW;
    float lm = -3.4e38f;
    for (int i = tid; i < 513; i += 128) lm = fmaxf(lm, row[i]);
    float m = blkMax<128>(lm, red);
    float ls = 0.f;
    for (int i = tid; i < 513; i += 128) {
        float e = __expf(row[i] - m);
        row[i] = e;
        ls += e;
    }
    float s = blkSum<128>(ls, red);
    float inv = 1.0f / s;
    for (int i = tid; i < 513; i += 128) row[i] *= inv;
}

// ---------------- phase 3: ctx = P @ V over the band --------------------------
// grid (S/64, H), block 256. V chunks + P tiles in smem, 4x4 register tiles.
__global__ void attn_ctx_kernel(const float* __restrict__ qkv, const float* __restrict__ sc,
                                float* __restrict__ ctx) {
    const int q0 = blockIdx.x * 64;
    const int h  = blockIdx.y;
    const int tid = threadIdx.x;  // 256
    __shared__ float Vs[64][65];
    __shared__ float Ps[64][65];
    const float* Vb = qkv + 2l * S_ * D_;

    const int qg = tid >> 4;   // 0..15 (4 q rows)
    const int dg = tid & 15;   // 0..15 (4 dims)

    float acc[4][4];
#pragma unroll
    for (int i = 0; i < 4; i++)
#pragma unroll
        for (int j = 0; j < 4; j++) acc[i][j] = 0.f;

    for (int ch = 0; ch < 9; ch++) {
        int jb = q0 - W_ + ch * 64;
        __syncthreads();
        for (int idx = tid; idx < 4096; idx += 256) {
            int r = idx >> 6, c = idx & 63;
            int j = jb + r;
            Vs[r][c] = (j >= 0 && j < S_) ? Vb[(long)j * D_ + h * DH_ + c] : 0.f;
            // P tile: row r = local q, col c = local key
            int jj = jb + c - (q0 + r) + W_;
            Ps[r][c] = (jj >= 0 && jj <= 2 * W_)
                       ? sc[((long)h * S_ + q0 + r) * SCW + jj] : 0.f;
        }
        __syncthreads();

#pragma unroll 8
        for (int kl = 0; kl < 64; kl++) {
            float pv[4], vv[4];
#pragma unroll
            for (int i = 0; i < 4; i++) pv[i] = Ps[qg * 4 + i][kl];
#pragma unroll
            for (int j = 0; j < 4; j++) vv[j] = Vs[kl][dg * 4 + j];
#pragma unroll
            for (int i = 0; i < 4; i++)
#pragma unroll
                for (int j = 0; j < 4; j++) acc[i][j] = fmaf(pv[i], vv[j], acc[i][j]);
        }
    }

#pragma unroll
    for (int i = 0; i < 4; i++)
#pragma unroll
        for (int j = 0; j < 4; j++)
            ctx[(long)(q0 + qg * 4 + i) * D_ + h * DH_ + dg * 4 + j] = acc[i][j];
}

// ---------------- pooled head: tanh(x[0] @ W + b) -----------------------------
__global__ void pool_kernel(const float* __restrict__ x, const float* __restrict__ Wp,
                            const float* __restrict__ bp, float* __restrict__ out) {
    __shared__ float x0[D_];
    int tid = threadIdx.x;  // 128
    for (int i = tid; i < D_; i += 128) x0[i] = x[i];
    __syncthreads();
    int e = blockIdx.x * 128 + tid;
    float acc = bp[e];
    for (int d = 0; d < D_; d++) acc = fmaf(x0[d], Wp[(long)d * D_ + e], acc);
    out[e] = tanhf(acc);
}

__global__ void copy_kernel(const float* __restrict__ in, float* __restrict__ out, int n) {
    int i = blockIdx.x * blockDim.x + threadIdx.x;
    if (i < n) out[i] = in[i];
}

// ---------------- launch -------------------------------------------------------
extern "C" void kernel_launch(void* const* d_in, const int* in_sizes, int n_in,
                              void* d_out, int out_size) {
    const int*   input_ids = (const int*)d_in[0];
    const int*   attn_mask = (const int*)d_in[1];
    const float* word_emb  = (const float*)d_in[2];
    const float* pos_emb   = (const float*)d_in[3];
    const float* type_emb  = (const float*)d_in[4];
    const float* emb_ln_s  = (const float*)d_in[5];
    const float* emb_ln_b  = (const float*)d_in[6];
    const float* Wqkv      = (const float*)d_in[7];
    const float* bqkv      = (const float*)d_in[8];
    const float* Wo        = (const float*)d_in[9];
    const float* bo        = (const float*)d_in[10];
    const float* ln1_s     = (const float*)d_in[11];
    const float* ln1_b     = (const float*)d_in[12];
    const float* W1        = (const float*)d_in[13];
    const float* b1        = (const float*)d_in[14];
    const float* W2        = (const float*)d_in[15];
    const float* b2        = (const float*)d_in[16];
    const float* ln2_s     = (const float*)d_in[17];
    const float* ln2_b     = (const float*)d_in[18];
    const float* pool_W    = (const float*)d_in[19];
    const float* pool_b    = (const float*)d_in[20];
    float* out = (float*)d_out;

    float *x, *qkv, *ctx, *y, *hbuf, *sc;
    int* pos;
    cudaGetSymbolAddress((void**)&x, g_x);
    cudaGetSymbolAddress((void**)&qkv, g_qkv);
    cudaGetSymbolAddress((void**)&ctx, g_ctx);
    cudaGetSymbolAddress((void**)&y, g_y);
    cudaGetSymbolAddress((void**)&hbuf, g_h);
    cudaGetSymbolAddress((void**)&sc, g_sc);
    cudaGetSymbolAddress((void**)&pos, g_pos);

    pos_kernel<<<1, 256>>>(attn_mask, pos);
    embed_ln_kernel<<<S_, 256>>>(input_ids, pos, word_emb, pos_emb, type_emb,
                                 emb_ln_s, emb_ln_b, x);

    for (int l = 0; l < L_; l++) {
        // QKV projections (TF32 tensor cores, 3xTF32)
        for (int t = 0; t < 3; t++) {
            tgemm_kernel<<<dim3(D_ / BN, S_ / BM), 256>>>(
                x, Wqkv + (long)(l * 3 + t) * D_ * D_,
                bqkv + (long)(l * 3 + t) * D_, nullptr,
                qkv + (long)t * S_ * D_, S_, D_, D_, 0);
        }
        // banded attention: scores -> softmax -> ctx
        attn_scores_kernel<<<dim3(S_ / 64, H_), 256>>>(qkv, attn_mask, sc);
        attn_softmax_kernel<<<dim3(S_, H_), 128>>>(sc);
        attn_ctx_kernel<<<dim3(S_ / 64, H_), 256>>>(qkv, sc, ctx);
        // output projection + residual, then LN
        tgemm_kernel<<<dim3(D_ / BN, S_ / BM), 256>>>(
            ctx, Wo + (long)l * D_ * D_, bo + (long)l * D_, x, y, S_, D_, D_, 0);
        ln_kernel<<<S_, 256>>>(y, ln1_s + (long)l * D_, ln1_b + (long)l * D_, x);
        // FFN
        tgemm_kernel<<<dim3(F_ / BN, S_ / BM), 256>>>(
            x, W1 + (long)l * D_ * F_, b1 + (long)l * F_, nullptr, hbuf, S_, F_, D_, 1);
        tgemm_kernel<<<dim3(D_ / BN, S_ / BM), 256>>>(
            hbuf, W2 + (long)l * F_ * D_, b2 + (long)l * D_, x, y, S_, D_, F_, 0);
        ln_kernel<<<S_, 256>>>(y, ln2_s + (long)l * D_, ln2_b + (long)l * D_, x);
    }

    copy_kernel<<<(S_ * D_ + 255) / 256, 256>>>(x, out, S_ * D_);
    pool_kernel<<<D_ / 128, 128>>>(x, pool_W, pool_b, out + (long)S_ * D_);
}

// round 11
// speedup vs baseline: 3.1101x; 2.7756x over previous
#include <cuda_runtime.h>
#include <cuda_bf16.h>
#include <math.h>
#include <stdint.h>
#include <mma.h>

using namespace nvcuda;

#define S_ 2048
#define D_ 768
#define H_ 12
#define DH_ 64
#define F_ 3072
#define L_ 2
#define W_ 256
#define SCW 520      // padded 2W+1=513 score-row stride
#define QKV_N 2304   // packed q|k|v output width

// ---------------- scratch (static device memory; no allocations) -------------
__device__ float g_x[S_ * D_];        // residual stream (fp32)
__device__ float g_qkv[3 * S_ * D_];  // q/k/v fp32, each [s][h*64+dh]
__device__ float g_y[S_ * D_];        // pre-LN buffer
__device__ float g_sc[H_ * S_ * SCW]; // banded attention scores/probs
__device__ int   g_pos[S_];

// bf16 hi/lo activation splits (GEMM inputs)
__device__ __nv_bfloat16 g_xh[S_ * D_], g_xl[S_ * D_];   // residual stream
__device__ __nv_bfloat16 g_ch[S_ * D_], g_cl[S_ * D_];   // attention ctx
__device__ __nv_bfloat16 g_hh[S_ * F_], g_hl[S_ * F_];   // FFN hidden

// bf16 hi/lo weight splits (built once per launch)
__device__ __nv_bfloat16 g_wqkv_h[L_ * D_ * QKV_N], g_wqkv_l[L_ * D_ * QKV_N];
__device__ __nv_bfloat16 g_wo_h[L_ * D_ * D_],      g_wo_l[L_ * D_ * D_];
__device__ __nv_bfloat16 g_w1_h[L_ * D_ * F_],      g_w1_l[L_ * D_ * F_];
__device__ __nv_bfloat16 g_w2_h[L_ * F_ * D_],      g_w2_l[L_ * F_ * D_];

// ---------------- helpers -----------------------------------------------------
__device__ __forceinline__ void bsplit(float v, __nv_bfloat16& hi, __nv_bfloat16& lo) {
    hi = __float2bfloat16(v);
    lo = __float2bfloat16(v - __bfloat162float(hi));
}

__device__ __forceinline__ void cpasync16(unsigned int dst, const void* src) {
    asm volatile("cp.async.cg.shared.global [%0], [%1], 16;" :: "r"(dst), "l"(src));
}
__device__ __forceinline__ void cp_commit() { asm volatile("cp.async.commit_group;"); }
__device__ __forceinline__ void cp_wait1()  { asm volatile("cp.async.wait_group 1;"); }

template <int NT>
__device__ __forceinline__ float blkSum(float v, float* red) {
    int tid = threadIdx.x;
    red[tid] = v; __syncthreads();
#pragma unroll
    for (int s = NT / 2; s > 0; s >>= 1) {
        if (tid < s) red[tid] += red[tid + s];
        __syncthreads();
    }
    float r = red[0]; __syncthreads();
    return r;
}

template <int NT>
__device__ __forceinline__ float blkMax(float v, float* red) {
    int tid = threadIdx.x;
    red[tid] = v; __syncthreads();
#pragma unroll
    for (int s = NT / 2; s > 0; s >>= 1) {
        if (tid < s) red[tid] = fmaxf(red[tid], red[tid + s]);
        __syncthreads();
    }
    float r = red[0]; __syncthreads();
    return r;
}

// ---------------- weight split kernels ----------------------------------------
// Wqkv [L][3][D][D] -> per-layer packed [K=D][N=3D] with n = t*D + e
__global__ void split_qkv_kernel(const float* __restrict__ src,
                                 __nv_bfloat16* __restrict__ hi, __nv_bfloat16* __restrict__ lo) {
    long i = (long)blockIdx.x * 256 + threadIdx.x;   // over L*3*D*D
    int e = i % D_;
    int d = (i / D_) % D_;
    int t = (i / ((long)D_ * D_)) % 3;
    int l = i / (3l * D_ * D_);
    long dst = (long)l * D_ * QKV_N + (long)d * QKV_N + t * D_ + e;
    bsplit(src[i], hi[dst], lo[dst]);
}

__global__ void split_plain_kernel(const float* __restrict__ src,
                                   __nv_bfloat16* __restrict__ hi, __nv_bfloat16* __restrict__ lo) {
    long i = (long)blockIdx.x * 256 + threadIdx.x;
    bsplit(src[i], hi[i], lo[i]);
}

// ---------------- pos ids: cumsum(mask)*mask + 1 ------------------------------
__global__ void pos_kernel(const int* __restrict__ mask, int* __restrict__ pos) {
    __shared__ int part[257];
    int tid = threadIdx.x;
    int c[8];
    int acc = 0;
#pragma unroll
    for (int i = 0; i < 8; i++) { acc += mask[tid * 8 + i]; c[i] = acc; }
    part[tid + 1] = acc;
    __syncthreads();
    if (tid == 0) {
        part[0] = 0;
        for (int i = 1; i <= 256; i++) part[i] += part[i - 1];
    }
    __syncthreads();
    int base = part[tid];
#pragma unroll
    for (int i = 0; i < 8; i++) {
        int idx = tid * 8 + i;
        pos[idx] = (base + c[i]) * mask[idx] + 1;
    }
}

// ---------------- embedding + LayerNorm (writes fp32 + bf16 split) ------------
__global__ void embed_ln_kernel(const int* __restrict__ ids, const int* __restrict__ pos,
                                const float* __restrict__ we, const float* __restrict__ pe,
                                const float* __restrict__ te,
                                const float* __restrict__ gs, const float* __restrict__ gb,
                                float* __restrict__ out,
                                __nv_bfloat16* __restrict__ oh, __nv_bfloat16* __restrict__ ol) {
    int row = blockIdx.x;
    int tid = threadIdx.x;  // 256
    __shared__ float buf[D_];
    __shared__ float red[256];
    const float* w = we + (long)ids[row] * D_;
    const float* p = pe + (long)pos[row] * D_;
    float lsum = 0.f, lsq = 0.f;
#pragma unroll
    for (int i = 0; i < 3; i++) {
        int d = tid + i * 256;
        float v = w[d] + p[d] + te[d];
        buf[d] = v;
        lsum += v; lsq += v * v;
    }
    float total = blkSum<256>(lsum, red);
    float totsq = blkSum<256>(lsq, red);
    float mean = total * (1.f / D_);
    float var  = totsq * (1.f / D_) - mean * mean;
    float inv  = rsqrtf(var + 1e-5f);
#pragma unroll
    for (int i = 0; i < 3; i++) {
        int d = tid + i * 256;
        float v = (buf[d] - mean) * inv * gs[d] + gb[d];
        long idx = (long)row * D_ + d;
        out[idx] = v;
        bsplit(v, oh[idx], ol[idx]);
    }
}

// ---------------- LayerNorm (writes fp32 + bf16 split) -------------------------
__global__ void ln_kernel(const float* __restrict__ in,
                          const float* __restrict__ gs, const float* __restrict__ gb,
                          float* __restrict__ out,
                          __nv_bfloat16* __restrict__ oh, __nv_bfloat16* __restrict__ ol) {
    int row = blockIdx.x;
    int tid = threadIdx.x;  // 256
    __shared__ float red[256];
    const float* r = in + (long)row * D_;
    float v0 = r[tid], v1 = r[tid + 256], v2 = r[tid + 512];
    float lsum = v0 + v1 + v2;
    float lsq = v0 * v0 + v1 * v1 + v2 * v2;
    float total = blkSum<256>(lsum, red);
    float totsq = blkSum<256>(lsq, red);
    float mean = total * (1.f / D_);
    float var  = totsq * (1.f / D_) - mean * mean;
    float inv  = rsqrtf(var + 1e-5f);
#pragma unroll
    for (int i = 0; i < 3; i++) {
        int d = tid + i * 256;
        float v = ((i == 0 ? v0 : (i == 1 ? v1 : v2)) - mean) * inv * gs[d] + gb[d];
        long idx = (long)row * D_ + d;
        out[idx] = v;
        bsplit(v, oh[idx], ol[idx]);
    }
}

// ---------------- bf16-split tensor-core GEMM ---------------------------------
// C[M,N] = epilogue(A @ B + bias), A = Ah+Al, B = Bh+Bl (bf16 hi/lo splits)
// 3 MMAs per k16: ah*bl + al*bh + ah*bh (lo*lo term ~2^-18, dropped)
// modes: 0 = fp32 out (+optional resid); 1 = gelu -> bf16 split out; 2 = qkv remap
#define BM 128
#define BN 128
#define BKq 32
#define LDA_ 40     // bf16 elems (32 + 8 pad)
#define LDB_ 136    // bf16 elems (128 + 8 pad)
#define ASTG (BM * LDA_)          // 5120 elems
#define BSTG (BKq * LDB_)         // 4352 elems
#define STG_ELE (2 * ASTG + 2 * BSTG)
#define STG_BYTES (STG_ELE * 2)   // 37888
#define GEMM_SMEM (2 * STG_BYTES) // 75776

// stage loader: issues 8x cp.async of 16B for A(hi/lo) and B(hi/lo) slabs
__device__ __forceinline__ void load_stage(
    unsigned int sb,
    const __nv_bfloat16* __restrict__ Ah, const __nv_bfloat16* __restrict__ Al,
    const __nv_bfloat16* __restrict__ Bh, const __nv_bfloat16* __restrict__ Bl,
    int bRow, int bCol, int arow, int akc, int brow, int bcol,
    int k0, int N, int K)
{
    const __nv_bfloat16* gah = Ah + (long)(bRow + arow) * K + k0 + akc;
    const __nv_bfloat16* gal = Al + (long)(bRow + arow) * K + k0 + akc;
    cpasync16(sb + (arow * LDA_ + akc) * 2, gah);
    cpasync16(sb + ((arow + 64) * LDA_ + akc) * 2, gah + 64l * K);
    cpasync16(sb + ASTG * 2 + (arow * LDA_ + akc) * 2, gal);
    cpasync16(sb + ASTG * 2 + ((arow + 64) * LDA_ + akc) * 2, gal + 64l * K);
    const __nv_bfloat16* gbh = Bh + (long)(k0 + brow) * N + bCol + bcol;
    const __nv_bfloat16* gbl = Bl + (long)(k0 + brow) * N + bCol + bcol;
    cpasync16(sb + 2 * ASTG * 2 + (brow * LDB_ + bcol) * 2, gbh);
    cpasync16(sb + 2 * ASTG * 2 + ((brow + 16) * LDB_ + bcol) * 2, gbh + 16l * N);
    cpasync16(sb + (2 * ASTG + BSTG) * 2 + (brow * LDB_ + bcol) * 2, gbl);
    cpasync16(sb + (2 * ASTG + BSTG) * 2 + ((brow + 16) * LDB_ + bcol) * 2, gbl + 16l * N);
}

__global__ __launch_bounds__(256, 2)
void tgemm_kernel(const __nv_bfloat16* __restrict__ Ah, const __nv_bfloat16* __restrict__ Al,
                  const __nv_bfloat16* __restrict__ Bh, const __nv_bfloat16* __restrict__ Bl,
                  const float* __restrict__ bias, const float* __restrict__ resid,
                  float* __restrict__ C,
                  __nv_bfloat16* __restrict__ Ch, __nv_bfloat16* __restrict__ Cl,
                  int M, int N, int K, int mode) {
    extern __shared__ __nv_bfloat16 smem[];
    const int tid  = threadIdx.x;
    const int lane = tid & 31;
    const int wid  = tid >> 5;       // 0..7
    const int wr   = wid >> 2;       // 0..1 : 64-row slab
    const int wc   = wid & 3;        // 0..3 : 32-col slab
    const int bRow = blockIdx.y * BM;
    const int bCol = blockIdx.x * BN;

    // cp.async mapping: A chunks (row, k8) and B chunks (krow, col8), 16B each
    const int arow = tid >> 2;         // 0..63 (also +64)
    const int akc  = (tid & 3) * 8;    // 0,8,16,24
    const int brow = tid >> 4;         // 0..15 (also +16)
    const int bcol = (tid & 15) * 8;   // 0..120

    const unsigned int smem_u = (unsigned int)__cvta_generic_to_shared(smem);

    wmma::fragment<wmma::accumulator, 16, 16, 16, float> acc[4][2];
#pragma unroll
    for (int i = 0; i < 4; i++)
#pragma unroll
        for (int j = 0; j < 2; j++) wmma::fill_fragment(acc[i][j], 0.0f);

    const int nt = K / BKq;

    load_stage(smem_u, Ah, Al, Bh, Bl, bRow, bCol, arow, akc, brow, bcol, 0, N, K);
    cp_commit();

    for (int t = 0; t < nt; t++) {
        if (t + 1 < nt)
            load_stage(smem_u + ((t + 1) & 1) * STG_BYTES, Ah, Al, Bh, Bl,
                       bRow, bCol, arow, akc, brow, bcol, (t + 1) * BKq, N, K);
        cp_commit();
        cp_wait1();
        __syncthreads();

        const __nv_bfloat16* base = smem + (t & 1) * STG_ELE;
#pragma unroll
        for (int ks = 0; ks < BKq; ks += 16) {
            wmma::fragment<wmma::matrix_a, 16, 16, 16, __nv_bfloat16, wmma::row_major> ah[4], al[4];
#pragma unroll
            for (int i = 0; i < 4; i++) {
                wmma::load_matrix_sync(ah[i], base + (wr * 64 + i * 16) * LDA_ + ks, LDA_);
                wmma::load_matrix_sync(al[i], base + ASTG + (wr * 64 + i * 16) * LDA_ + ks, LDA_);
            }
#pragma unroll
            for (int j = 0; j < 2; j++) {
                wmma::fragment<wmma::matrix_b, 16, 16, 16, __nv_bfloat16, wmma::row_major> bh, bl;
                wmma::load_matrix_sync(bh, base + 2 * ASTG + ks * LDB_ + wc * 32 + j * 16, LDB_);
                wmma::load_matrix_sync(bl, base + 2 * ASTG + BSTG + ks * LDB_ + wc * 32 + j * 16, LDB_);
#pragma unroll
                for (int i = 0; i < 4; i++) {
                    wmma::mma_sync(acc[i][j], ah[i], bl, acc[i][j]);
                    wmma::mma_sync(acc[i][j], al[i], bh, acc[i][j]);
                    wmma::mma_sync(acc[i][j], ah[i], bh, acc[i][j]);
                }
            }
        }
        __syncthreads();
    }

    // epilogue: per-warp staging through (reused) smem
    float* ws = (float*)smem + wid * (16 * 36);
    const int gc = bCol + wc * 32 + lane;
#pragma unroll
    for (int mi = 0; mi < 4; mi++) {
        wmma::store_matrix_sync(ws,      acc[mi][0], 36, wmma::mem_row_major);
        wmma::store_matrix_sync(ws + 16, acc[mi][1], 36, wmma::mem_row_major);
        __syncwarp();
        const int gr0 = bRow + wr * 64 + mi * 16;
#pragma unroll
        for (int r = 0; r < 16; r++) {
            float v = ws[r * 36 + lane] + bias[gc];
            long idx = (long)(gr0 + r) * N + gc;
            if (mode == 0) {
                if (resid) v += resid[idx];
                C[idx] = v;
            } else if (mode == 1) {
                v = 0.5f * v * (1.0f + erff(v * 0.70710678118654752f));
                bsplit(v, Ch[idx], Cl[idx]);
            } else {  // mode 2: packed qkv -> [t][s][e]
                int tq = gc / D_;
                C[(long)tq * S_ * D_ + (long)(gr0 + r) * D_ + (gc - tq * D_)] = v;
            }
        }
        __syncwarp();
    }
}

// ---------------- banded attention, phase 1: scores ---------------------------
__global__ void attn_scores_kernel(const float* __restrict__ qkv, const int* __restrict__ mask,
                                   float* __restrict__ sc) {
    const int q0 = blockIdx.x * 64;
    const int h  = blockIdx.y;
    const int tid = threadIdx.x;  // 256
    __shared__ float Qs[64][65];
    __shared__ float Ks[64][65];
    __shared__ int   sm[64];
    const float* Kb = qkv + (long)S_ * D_;

    for (int idx = tid; idx < 4096; idx += 256) {
        int r = idx >> 6, c = idx & 63;
        Qs[r][c] = qkv[(long)(q0 + r) * D_ + h * DH_ + c] * 0.125f;
    }

    const int qg = tid >> 4;
    const int kg = tid & 15;

    for (int ch = 0; ch < 9; ch++) {
        int jb = q0 - W_ + ch * 64;
        __syncthreads();
        for (int idx = tid; idx < 4096; idx += 256) {
            int r = idx >> 6, c = idx & 63;
            int j = jb + r;
            Ks[r][c] = (j >= 0 && j < S_) ? Kb[(long)j * D_ + h * DH_ + c] : 0.f;
        }
        if (tid < 64) {
            int j = jb + tid;
            sm[tid] = (j >= 0 && j < S_) ? mask[j] : 0;
        }
        __syncthreads();

        float accs[4][4];
#pragma unroll
        for (int i = 0; i < 4; i++)
#pragma unroll
            for (int j = 0; j < 4; j++) accs[i][j] = 0.f;

#pragma unroll 8
        for (int d = 0; d < 64; d++) {
            float qv[4], kv[4];
#pragma unroll
            for (int i = 0; i < 4; i++) qv[i] = Qs[qg * 4 + i][d];
#pragma unroll
            for (int j = 0; j < 4; j++) kv[j] = Ks[kg * 4 + j][d];
#pragma unroll
            for (int i = 0; i < 4; i++)
#pragma unroll
                for (int j = 0; j < 4; j++) accs[i][j] = fmaf(qv[i], kv[j], accs[i][j]);
        }

#pragma unroll
        for (int i = 0; i < 4; i++) {
            int q = q0 + qg * 4 + i;
#pragma unroll
            for (int j = 0; j < 4; j++) {
                int jg = jb + kg * 4 + j;
                int jj = jg - q + W_;
                if (jj >= 0 && jj <= 2 * W_) {
                    float v = sm[kg * 4 + j] ? accs[i][j] : -1e9f;
                    sc[((long)h * S_ + q) * SCW + jj] = v;
                }
            }
        }
    }
}

// ---------------- phase 2: rowwise softmax ------------------------------------
__global__ void attn_softmax_kernel(float* __restrict__ sc) {
    const int q = blockIdx.x;
    const int h = blockIdx.y;
    const int tid = threadIdx.x;  // 128
    __shared__ float red[128];
    float* row = sc + ((long)h * S_ + q) * SCW;
    float lm = -3.4e38f;
    for (int i = tid; i < 513; i += 128) lm = fmaxf(lm, row[i]);
    float m = blkMax<128>(lm, red);
    float ls = 0.f;
    for (int i = tid; i < 513; i += 128) {
        float e = __expf(row[i] - m);
        row[i] = e;
        ls += e;
    }
    float s = blkSum<128>(ls, red);
    float inv = 1.0f / s;
    for (int i = tid; i < 513; i += 128) row[i] *= inv;
}

// ---------------- phase 3: ctx = P @ V (writes bf16 split) --------------------
__global__ void attn_ctx_kernel(const float* __restrict__ qkv, const float* __restrict__ sc,
                                __nv_bfloat16* __restrict__ ch, __nv_bfloat16* __restrict__ cl) {
    const int q0 = blockIdx.x * 64;
    const int h  = blockIdx.y;
    const int tid = threadIdx.x;  // 256
    __shared__ float Vs[64][65];
    __shared__ float Ps[64][65];
    const float* Vb = qkv + 2l * S_ * D_;

    const int qg = tid >> 4;
    const int dg = tid & 15;

    float acc[4][4];
#pragma unroll
    for (int i = 0; i < 4; i++)
#pragma unroll
        for (int j = 0; j < 4; j++) acc[i][j] = 0.f;

    for (int ch9 = 0; ch9 < 9; ch9++) {
        int jb = q0 - W_ + ch9 * 64;
        __syncthreads();
        for (int idx = tid; idx < 4096; idx += 256) {
            int r = idx >> 6, c = idx & 63;
            int j = jb + r;
            Vs[r][c] = (j >= 0 && j < S_) ? Vb[(long)j * D_ + h * DH_ + c] : 0.f;
            int jj = jb + c - (q0 + r) + W_;
            Ps[r][c] = (jj >= 0 && jj <= 2 * W_)
                       ? sc[((long)h * S_ + q0 + r) * SCW + jj] : 0.f;
        }
        __syncthreads();

#pragma unroll 8
        for (int kl = 0; kl < 64; kl++) {
            float pv[4], vv[4];
#pragma unroll
            for (int i = 0; i < 4; i++) pv[i] = Ps[qg * 4 + i][kl];
#pragma unroll
            for (int j = 0; j < 4; j++) vv[j] = Vs[kl][dg * 4 + j];
#pragma unroll
            for (int i = 0; i < 4; i++)
#pragma unroll
                for (int j = 0; j < 4; j++) acc[i][j] = fmaf(pv[i], vv[j], acc[i][j]);
        }
    }

#pragma unroll
    for (int i = 0; i < 4; i++)
#pragma unroll
        for (int j = 0; j < 4; j++) {
            long idx = (long)(q0 + qg * 4 + i) * D_ + h * DH_ + dg * 4 + j;
            bsplit(acc[i][j], ch[idx], cl[idx]);
        }
}

// ---------------- pooled head -------------------------------------------------
__global__ void pool_kernel(const float* __restrict__ x, const float* __restrict__ Wp,
                            const float* __restrict__ bp, float* __restrict__ out) {
    __shared__ float x0[D_];
    int tid = threadIdx.x;  // 128
    for (int i = tid; i < D_; i += 128) x0[i] = x[i];
    __syncthreads();
    int e = blockIdx.x * 128 + tid;
    float acc = bp[e];
    for (int d = 0; d < D_; d++) acc = fmaf(x0[d], Wp[(long)d * D_ + e], acc);
    out[e] = tanhf(acc);
}

__global__ void copy_kernel(const float* __restrict__ in, float* __restrict__ out, int n) {
    int i = blockIdx.x * blockDim.x + threadIdx.x;
    if (i < n) out[i] = in[i];
}

// ---------------- launch -------------------------------------------------------
extern "C" void kernel_launch(void* const* d_in, const int* in_sizes, int n_in,
                              void* d_out, int out_size) {
    const int*   input_ids = (const int*)d_in[0];
    const int*   attn_mask = (const int*)d_in[1];
    const float* word_emb  = (const float*)d_in[2];
    const float* pos_emb   = (const float*)d_in[3];
    const float* type_emb  = (const float*)d_in[4];
    const float* emb_ln_s  = (const float*)d_in[5];
    const float* emb_ln_b  = (const float*)d_in[6];
    const float* Wqkv      = (const float*)d_in[7];
    const float* bqkv      = (const float*)d_in[8];
    const float* Wo        = (const float*)d_in[9];
    const float* bo        = (const float*)d_in[10];
    const float* ln1_s     = (const float*)d_in[11];
    const float* ln1_b     = (const float*)d_in[12];
    const float* W1        = (const float*)d_in[13];
    const float* b1        = (const float*)d_in[14];
    const float* W2        = (const float*)d_in[15];
    const float* b2        = (const float*)d_in[16];
    const float* ln2_s     = (const float*)d_in[17];
    const float* ln2_b     = (const float*)d_in[18];
    const float* pool_W    = (const float*)d_in[19];
    const float* pool_b    = (const float*)d_in[20];
    float* out = (float*)d_out;

    float *x, *qkv, *y, *sc;
    int* pos;
    __nv_bfloat16 *xh, *xl, *ch, *cl, *hh, *hl;
    __nv_bfloat16 *wqh, *wql, *woh, *wol, *w1h, *w1l, *w2h, *w2l;
    cudaGetSymbolAddress((void**)&x, g_x);
    cudaGetSymbolAddress((void**)&qkv, g_qkv);
    cudaGetSymbolAddress((void**)&y, g_y);
    cudaGetSymbolAddress((void**)&sc, g_sc);
    cudaGetSymbolAddress((void**)&pos, g_pos);
    cudaGetSymbolAddress((void**)&xh, g_xh); cudaGetSymbolAddress((void**)&xl, g_xl);
    cudaGetSymbolAddress((void**)&ch, g_ch); cudaGetSymbolAddress((void**)&cl, g_cl);
    cudaGetSymbolAddress((void**)&hh, g_hh); cudaGetSymbolAddress((void**)&hl, g_hl);
    cudaGetSymbolAddress((void**)&wqh, g_wqkv_h); cudaGetSymbolAddress((void**)&wql, g_wqkv_l);
    cudaGetSymbolAddress((void**)&woh, g_wo_h);   cudaGetSymbolAddress((void**)&wol, g_wo_l);
    cudaGetSymbolAddress((void**)&w1h, g_w1_h);   cudaGetSymbolAddress((void**)&w1l, g_w1_l);
    cudaGetSymbolAddress((void**)&w2h, g_w2_h);   cudaGetSymbolAddress((void**)&w2l, g_w2_l);

    cudaFuncSetAttribute(tgemm_kernel, cudaFuncAttributeMaxDynamicSharedMemorySize, GEMM_SMEM);

    // one-time (per launch) weight splits
    split_qkv_kernel<<<(L_ * 3 * D_ * D_) / 256, 256>>>(Wqkv, wqh, wql);
    split_plain_kernel<<<(L_ * D_ * D_) / 256, 256>>>(Wo, woh, wol);
    split_plain_kernel<<<(L_ * D_ * F_) / 256, 256>>>(W1, w1h, w1l);
    split_plain_kernel<<<(L_ * F_ * D_) / 256, 256>>>(W2, w2h, w2l);

    pos_kernel<<<1, 256>>>(attn_mask, pos);
    embed_ln_kernel<<<S_, 256>>>(input_ids, pos, word_emb, pos_emb, type_emb,
                                 emb_ln_s, emb_ln_b, x, xh, xl);

    for (int l = 0; l < L_; l++) {
        // fused QKV projection (N = 2304, qkv-remap epilogue)
        tgemm_kernel<<<dim3(QKV_N / BN, S_ / BM), 256, GEMM_SMEM>>>(
            xh, xl, wqh + (long)l * D_ * QKV_N, wql + (long)l * D_ * QKV_N,
            bqkv + (long)l * QKV_N, nullptr, qkv, nullptr, nullptr,
            S_, QKV_N, D_, 2);
        // banded attention
        attn_scores_kernel<<<dim3(S_ / 64, H_), 256>>>(qkv, attn_mask, sc);
        attn_softmax_kernel<<<dim3(S_, H_), 128>>>(sc);
        attn_ctx_kernel<<<dim3(S_ / 64, H_), 256>>>(qkv, sc, ch, cl);
        // output projection + residual -> LN
        tgemm_kernel<<<dim3(D_ / BN, S_ / BM), 256, GEMM_SMEM>>>(
            ch, cl, woh + (long)l * D_ * D_, wol + (long)l * D_ * D_,
            bo + (long)l * D_, x, y, nullptr, nullptr, S_, D_, D_, 0);
        ln_kernel<<<S_, 256>>>(y, ln1_s + (long)l * D_, ln1_b + (long)l * D_, x, xh, xl);
        // FFN: W1 (gelu -> bf16 split), W2 (+resid) -> LN
        tgemm_kernel<<<dim3(F_ / BN, S_ / BM), 256, GEMM_SMEM>>>(
            xh, xl, w1h + (long)l * D_ * F_, w1l + (long)l * D_ * F_,
            b1 + (long)l * F_, nullptr, nullptr, hh, hl, S_, F_, D_, 1);
        tgemm_kernel<<<dim3(D_ / BN, S_ / BM), 256, GEMM_SMEM>>>(
            hh, hl, w2h + (long)l * F_ * D_, w2l + (long)l * F_ * D_,
            b2 + (long)l * D_, x, y, nullptr, nullptr, S_, D_, F_, 0);
        ln_kernel<<<S_, 256>>>(y, ln2_s + (long)l * D_, ln2_b + (long)l * D_, x, xh, xl);
    }

    copy_kernel<<<(S_ * D_ + 255) / 256, 256>>>(x, out, S_ * D_);
    pool_kernel<<<D_ / 128, 128>>>(x, pool_W, pool_b, out + (long)S_ * D_);
}

// round 13
// speedup vs baseline: 3.5731x; 1.1489x over previous
#include <cuda_runtime.h>
#include <cuda_bf16.h>
#include <math.h>
#include <stdint.h>
#include <mma.h>

using namespace nvcuda;

#define S_ 2048
#define D_ 768
#define H_ 12
#define DH_ 64
#define F_ 3072
#define L_ 2
#define W_ 256
#define QKV_N 2304   // packed q|k|v output width

// ---------------- scratch (static device memory; no allocations) -------------
__device__ float g_x[S_ * D_];        // residual stream (fp32)
__device__ float g_qkv[3 * S_ * D_];  // q/k/v fp32, each [s][h*64+dh]
__device__ float g_y[S_ * D_];        // pre-LN buffer
__device__ int   g_pos[S_];

// bf16 hi/lo activation splits (GEMM inputs)
__device__ __nv_bfloat16 g_xh[S_ * D_], g_xl[S_ * D_];   // residual stream
__device__ __nv_bfloat16 g_ch[S_ * D_], g_cl[S_ * D_];   // attention ctx
__device__ __nv_bfloat16 g_hh[S_ * F_], g_hl[S_ * F_];   // FFN hidden

// bf16 hi/lo weight splits (built once per launch)
__device__ __nv_bfloat16 g_wqkv_h[L_ * D_ * QKV_N], g_wqkv_l[L_ * D_ * QKV_N];
__device__ __nv_bfloat16 g_wo_h[L_ * D_ * D_],      g_wo_l[L_ * D_ * D_];
__device__ __nv_bfloat16 g_w1_h[L_ * D_ * F_],      g_w1_l[L_ * D_ * F_];
__device__ __nv_bfloat16 g_w2_h[L_ * F_ * D_],      g_w2_l[L_ * F_ * D_];

// ---------------- helpers -----------------------------------------------------
__device__ __forceinline__ void bsplit(float v, __nv_bfloat16& hi, __nv_bfloat16& lo) {
    hi = __float2bfloat16(v);
    lo = __float2bfloat16(v - __bfloat162float(hi));
}

__device__ __forceinline__ void cpasync16(unsigned int dst, const void* src) {
    asm volatile("cp.async.cg.shared.global [%0], [%1], 16;" :: "r"(dst), "l"(src));
}
__device__ __forceinline__ void cp_commit() { asm volatile("cp.async.commit_group;"); }
__device__ __forceinline__ void cp_wait1()  { asm volatile("cp.async.wait_group 1;"); }

template <int NT>
__device__ __forceinline__ float blkSum(float v, float* red) {
    int tid = threadIdx.x;
    red[tid] = v; __syncthreads();
#pragma unroll
    for (int s = NT / 2; s > 0; s >>= 1) {
        if (tid < s) red[tid] += red[tid + s];
        __syncthreads();
    }
    float r = red[0]; __syncthreads();
    return r;
}

// ---------------- weight split kernels ----------------------------------------
// Wqkv [L][3][D][D] -> per-layer packed [K=D][N=3D] with n = t*D + e
__global__ void split_qkv_kernel(const float* __restrict__ src,
                                 __nv_bfloat16* __restrict__ hi, __nv_bfloat16* __restrict__ lo) {
    long i = (long)blockIdx.x * 256 + threadIdx.x;   // over L*3*D*D
    int e = i % D_;
    int d = (i / D_) % D_;
    int t = (i / ((long)D_ * D_)) % 3;
    int l = i / (3l * D_ * D_);
    long dst = (long)l * D_ * QKV_N + (long)d * QKV_N + t * D_ + e;
    bsplit(src[i], hi[dst], lo[dst]);
}

__global__ void split_plain_kernel(const float* __restrict__ src,
                                   __nv_bfloat16* __restrict__ hi, __nv_bfloat16* __restrict__ lo) {
    long i = (long)blockIdx.x * 256 + threadIdx.x;
    bsplit(src[i], hi[i], lo[i]);
}

// ---------------- pos ids: cumsum(mask)*mask + 1 ------------------------------
__global__ void pos_kernel(const int* __restrict__ mask, int* __restrict__ pos) {
    __shared__ int part[257];
    int tid = threadIdx.x;
    int c[8];
    int acc = 0;
#pragma unroll
    for (int i = 0; i < 8; i++) { acc += mask[tid * 8 + i]; c[i] = acc; }
    part[tid + 1] = acc;
    __syncthreads();
    if (tid == 0) {
        part[0] = 0;
        for (int i = 1; i <= 256; i++) part[i] += part[i - 1];
    }
    __syncthreads();
    int base = part[tid];
#pragma unroll
    for (int i = 0; i < 8; i++) {
        int idx = tid * 8 + i;
        pos[idx] = (base + c[i]) * mask[idx] + 1;
    }
}

// ---------------- embedding + LayerNorm (writes fp32 + bf16 split) ------------
__global__ void embed_ln_kernel(const int* __restrict__ ids, const int* __restrict__ pos,
                                const float* __restrict__ we, const float* __restrict__ pe,
                                const float* __restrict__ te,
                                const float* __restrict__ gs, const float* __restrict__ gb,
                                float* __restrict__ out,
                                __nv_bfloat16* __restrict__ oh, __nv_bfloat16* __restrict__ ol) {
    int row = blockIdx.x;
    int tid = threadIdx.x;  // 256
    __shared__ float buf[D_];
    __shared__ float red[256];
    const float* w = we + (long)ids[row] * D_;
    const float* p = pe + (long)pos[row] * D_;
    float lsum = 0.f, lsq = 0.f;
#pragma unroll
    for (int i = 0; i < 3; i++) {
        int d = tid + i * 256;
        float v = w[d] + p[d] + te[d];
        buf[d] = v;
        lsum += v; lsq += v * v;
    }
    float total = blkSum<256>(lsum, red);
    float totsq = blkSum<256>(lsq, red);
    float mean = total * (1.f / D_);
    float var  = totsq * (1.f / D_) - mean * mean;
    float inv  = rsqrtf(var + 1e-5f);
#pragma unroll
    for (int i = 0; i < 3; i++) {
        int d = tid + i * 256;
        float v = (buf[d] - mean) * inv * gs[d] + gb[d];
        long idx = (long)row * D_ + d;
        out[idx] = v;
        bsplit(v, oh[idx], ol[idx]);
    }
}

// ---------------- LayerNorm (writes fp32 + bf16 split) -------------------------
__global__ void ln_kernel(const float* __restrict__ in,
                          const float* __restrict__ gs, const float* __restrict__ gb,
                          float* __restrict__ out,
                          __nv_bfloat16* __restrict__ oh, __nv_bfloat16* __restrict__ ol) {
    int row = blockIdx.x;
    int tid = threadIdx.x;  // 256
    __shared__ float red[256];
    const float* r = in + (long)row * D_;
    float v0 = r[tid], v1 = r[tid + 256], v2 = r[tid + 512];
    float lsum = v0 + v1 + v2;
    float lsq = v0 * v0 + v1 * v1 + v2 * v2;
    float total = blkSum<256>(lsum, red);
    float totsq = blkSum<256>(lsq, red);
    float mean = total * (1.f / D_);
    float var  = totsq * (1.f / D_) - mean * mean;
    float inv  = rsqrtf(var + 1e-5f);
#pragma unroll
    for (int i = 0; i < 3; i++) {
        int d = tid + i * 256;
        float v = ((i == 0 ? v0 : (i == 1 ? v1 : v2)) - mean) * inv * gs[d] + gb[d];
        long idx = (long)row * D_ + d;
        out[idx] = v;
        bsplit(v, oh[idx], ol[idx]);
    }
}

// ---------------- bf16-split tensor-core GEMM ---------------------------------
#define BM 128
#define BN 128
#define BKq 32
#define LDA_ 40     // bf16 elems (32 + 8 pad)
#define LDB_ 136    // bf16 elems (128 + 8 pad)
#define ASTG (BM * LDA_)          // 5120 elems
#define BSTG (BKq * LDB_)         // 4352 elems
#define STG_ELE (2 * ASTG + 2 * BSTG)
#define STG_BYTES (STG_ELE * 2)   // 37888
#define GEMM_SMEM (2 * STG_BYTES) // 75776

__device__ __forceinline__ void load_stage(
    unsigned int sb,
    const __nv_bfloat16* __restrict__ Ah, const __nv_bfloat16* __restrict__ Al,
    const __nv_bfloat16* __restrict__ Bh, const __nv_bfloat16* __restrict__ Bl,
    int bRow, int bCol, int arow, int akc, int brow, int bcol,
    int k0, int N, int K)
{
    const __nv_bfloat16* gah = Ah + (long)(bRow + arow) * K + k0 + akc;
    const __nv_bfloat16* gal = Al + (long)(bRow + arow) * K + k0 + akc;
    cpasync16(sb + (arow * LDA_ + akc) * 2, gah);
    cpasync16(sb + ((arow + 64) * LDA_ + akc) * 2, gah + 64l * K);
    cpasync16(sb + ASTG * 2 + (arow * LDA_ + akc) * 2, gal);
    cpasync16(sb + ASTG * 2 + ((arow + 64) * LDA_ + akc) * 2, gal + 64l * K);
    const __nv_bfloat16* gbh = Bh + (long)(k0 + brow) * N + bCol + bcol;
    const __nv_bfloat16* gbl = Bl + (long)(k0 + brow) * N + bCol + bcol;
    cpasync16(sb + 2 * ASTG * 2 + (brow * LDB_ + bcol) * 2, gbh);
    cpasync16(sb + 2 * ASTG * 2 + ((brow + 16) * LDB_ + bcol) * 2, gbh + 16l * N);
    cpasync16(sb + (2 * ASTG + BSTG) * 2 + (brow * LDB_ + bcol) * 2, gbl);
    cpasync16(sb + (2 * ASTG + BSTG) * 2 + ((brow + 16) * LDB_ + bcol) * 2, gbl + 16l * N);
}

__global__ __launch_bounds__(256, 2)
void tgemm_kernel(const __nv_bfloat16* __restrict__ Ah, const __nv_bfloat16* __restrict__ Al,
                  const __nv_bfloat16* __restrict__ Bh, const __nv_bfloat16* __restrict__ Bl,
                  const float* __restrict__ bias, const float* __restrict__ resid,
                  float* __restrict__ C,
                  __nv_bfloat16* __restrict__ Ch, __nv_bfloat16* __restrict__ Cl,
                  int M, int N, int K, int mode) {
    extern __shared__ __nv_bfloat16 smem[];
    const int tid  = threadIdx.x;
    const int lane = tid & 31;
    const int wid  = tid >> 5;       // 0..7
    const int wr   = wid >> 2;       // 0..1 : 64-row slab
    const int wc   = wid & 3;        // 0..3 : 32-col slab
    const int bRow = blockIdx.y * BM;
    const int bCol = blockIdx.x * BN;

    const int arow = tid >> 2;         // 0..63 (also +64)
    const int akc  = (tid & 3) * 8;    // 0,8,16,24
    const int brow = tid >> 4;         // 0..15 (also +16)
    const int bcol = (tid & 15) * 8;   // 0..120

    const unsigned int smem_u = (unsigned int)__cvta_generic_to_shared(smem);

    wmma::fragment<wmma::accumulator, 16, 16, 16, float> acc[4][2];
#pragma unroll
    for (int i = 0; i < 4; i++)
#pragma unroll
        for (int j = 0; j < 2; j++) wmma::fill_fragment(acc[i][j], 0.0f);

    const int nt = K / BKq;

    load_stage(smem_u, Ah, Al, Bh, Bl, bRow, bCol, arow, akc, brow, bcol, 0, N, K);
    cp_commit();

    for (int t = 0; t < nt; t++) {
        if (t + 1 < nt)
            load_stage(smem_u + ((t + 1) & 1) * STG_BYTES, Ah, Al, Bh, Bl,
                       bRow, bCol, arow, akc, brow, bcol, (t + 1) * BKq, N, K);
        cp_commit();
        cp_wait1();
        __syncthreads();

        const __nv_bfloat16* base = smem + (t & 1) * STG_ELE;
#pragma unroll
        for (int ks = 0; ks < BKq; ks += 16) {
            wmma::fragment<wmma::matrix_a, 16, 16, 16, __nv_bfloat16, wmma::row_major> ah[4], al[4];
#pragma unroll
            for (int i = 0; i < 4; i++) {
                wmma::load_matrix_sync(ah[i], base + (wr * 64 + i * 16) * LDA_ + ks, LDA_);
                wmma::load_matrix_sync(al[i], base + ASTG + (wr * 64 + i * 16) * LDA_ + ks, LDA_);
            }
#pragma unroll
            for (int j = 0; j < 2; j++) {
                wmma::fragment<wmma::matrix_b, 16, 16, 16, __nv_bfloat16, wmma::row_major> bh, bl;
                wmma::load_matrix_sync(bh, base + 2 * ASTG + ks * LDB_ + wc * 32 + j * 16, LDB_);
                wmma::load_matrix_sync(bl, base + 2 * ASTG + BSTG + ks * LDB_ + wc * 32 + j * 16, LDB_);
#pragma unroll
                for (int i = 0; i < 4; i++) {
                    wmma::mma_sync(acc[i][j], ah[i], bl, acc[i][j]);
                    wmma::mma_sync(acc[i][j], al[i], bh, acc[i][j]);
                    wmma::mma_sync(acc[i][j], ah[i], bh, acc[i][j]);
                }
            }
        }
        __syncthreads();
    }

    // epilogue: per-warp staging through (reused) smem
    float* ws = (float*)smem + wid * (16 * 36);
    const int gc = bCol + wc * 32 + lane;
#pragma unroll
    for (int mi = 0; mi < 4; mi++) {
        wmma::store_matrix_sync(ws,      acc[mi][0], 36, wmma::mem_row_major);
        wmma::store_matrix_sync(ws + 16, acc[mi][1], 36, wmma::mem_row_major);
        __syncwarp();
        const int gr0 = bRow + wr * 64 + mi * 16;
#pragma unroll
        for (int r = 0; r < 16; r++) {
            float v = ws[r * 36 + lane] + bias[gc];
            long idx = (long)(gr0 + r) * N + gc;
            if (mode == 0) {
                if (resid) v += resid[idx];
                C[idx] = v;
            } else if (mode == 1) {
                v = 0.5f * v * (1.0f + erff(v * 0.70710678118654752f));
                bsplit(v, Ch[idx], Cl[idx]);
            } else {  // mode 2: packed qkv -> [t][s][e]
                int tq = gc / D_;
                C[(long)tq * S_ * D_ + (long)(gr0 + r) * D_ + (gc - tq * D_)] = v;
            }
        }
        __syncwarp();
    }
}

// ---------------- fused banded flash attention --------------------------------
// grid (S/64, H), 256 threads. Online softmax over 9 k-chunks of 64.
// Thread (qg, tg): rows qg*4..+3; tg = key-group in score phase, dim-group in PV.
#define AT_LDQ 65
#define AT_LDK 68
#define ATTN_SMEM ((64 * AT_LDQ + 2 * 64 * AT_LDK) * 4)   // 51456 bytes

__global__ __launch_bounds__(256)
void attn_fused_kernel(const float* __restrict__ qkv, const int* __restrict__ mask,
                       __nv_bfloat16* __restrict__ ch, __nv_bfloat16* __restrict__ cl) {
    extern __shared__ float asm_[];
    float* Qs  = asm_;                      // [64][AT_LDQ]
    float* KVs = asm_ + 64 * AT_LDQ;        // [64][AT_LDK] : K^T, then V
    float* Ps  = KVs + 64 * AT_LDK;         // [64][AT_LDK]
    __shared__ int smask[64];

    const int q0  = blockIdx.x * 64;
    const int h   = blockIdx.y;
    const int tid = threadIdx.x;
    const int qg  = tid >> 4;   // 0..15
    const int tg  = tid & 15;   // 0..15

    const float* Qb = qkv;
    const float* Kb = qkv + (long)S_ * D_;
    const float* Vb = qkv + 2l * S_ * D_;

    // Q tile (scale folded)
    for (int idx = tid; idx < 4096; idx += 256) {
        int r = idx >> 6, c = idx & 63;
        Qs[r * AT_LDQ + c] = Qb[(long)(q0 + r) * D_ + h * DH_ + c] * 0.125f;
    }

    float m[4], l[4], acc[4][4];
#pragma unroll
    for (int i = 0; i < 4; i++) {
        m[i] = -1e30f; l[i] = 0.f;
#pragma unroll
        for (int j = 0; j < 4; j++) acc[i][j] = 0.f;
    }

    for (int c9 = 0; c9 < 9; c9++) {
        const int jb = q0 - W_ + c9 * 64;
        __syncthreads();  // Qs ready (first iter) / prior Ps & V reads done

        // K chunk -> transposed smem KVs[d][j] (conflict-free col reads later)
        {
            int j  = tid & 63;
            int gj = jb + j;
            bool ok = (gj >= 0 && gj < S_);
            const float* kr = Kb + (long)gj * D_ + h * DH_;
            for (int d4 = (tid >> 6) * 4; d4 < 64; d4 += 16) {
                float4 k4 = ok ? *(const float4*)(kr + d4) : make_float4(0.f, 0.f, 0.f, 0.f);
                KVs[(d4 + 0) * AT_LDK + j] = k4.x;
                KVs[(d4 + 1) * AT_LDK + j] = k4.y;
                KVs[(d4 + 2) * AT_LDK + j] = k4.z;
                KVs[(d4 + 3) * AT_LDK + j] = k4.w;
            }
            if (tid < 64) smask[tid] = (jb + tid >= 0 && jb + tid < S_) ? mask[jb + tid] : 0;
        }
        __syncthreads();

        // S = Q @ K^T, 4x4 per thread
        float s[4][4];
#pragma unroll
        for (int i = 0; i < 4; i++)
#pragma unroll
            for (int j = 0; j < 4; j++) s[i][j] = 0.f;
        for (int d = 0; d < 64; d++) {
            float4 kv = *(const float4*)&KVs[d * AT_LDK + tg * 4];
            float q0v = Qs[(qg * 4 + 0) * AT_LDQ + d];
            float q1v = Qs[(qg * 4 + 1) * AT_LDQ + d];
            float q2v = Qs[(qg * 4 + 2) * AT_LDQ + d];
            float q3v = Qs[(qg * 4 + 3) * AT_LDQ + d];
            s[0][0] = fmaf(q0v, kv.x, s[0][0]); s[0][1] = fmaf(q0v, kv.y, s[0][1]);
            s[0][2] = fmaf(q0v, kv.z, s[0][2]); s[0][3] = fmaf(q0v, kv.w, s[0][3]);
            s[1][0] = fmaf(q1v, kv.x, s[1][0]); s[1][1] = fmaf(q1v, kv.y, s[1][1]);
            s[1][2] = fmaf(q1v, kv.z, s[1][2]); s[1][3] = fmaf(q1v, kv.w, s[1][3]);
            s[2][0] = fmaf(q2v, kv.x, s[2][0]); s[2][1] = fmaf(q2v, kv.y, s[2][1]);
            s[2][2] = fmaf(q2v, kv.z, s[2][2]); s[2][3] = fmaf(q2v, kv.w, s[2][3]);
            s[3][0] = fmaf(q3v, kv.x, s[3][0]); s[3][1] = fmaf(q3v, kv.y, s[3][1]);
            s[3][2] = fmaf(q3v, kv.z, s[3][2]); s[3][3] = fmaf(q3v, kv.w, s[3][3]);
        }

        // band+mask, online softmax update (row group = 16 lanes sharing qg)
#pragma unroll
        for (int i = 0; i < 4; i++) {
            int q = q0 + qg * 4 + i;
            float sv[4];
            float cm = -1e30f;
#pragma unroll
            for (int j = 0; j < 4; j++) {
                int gj = jb + tg * 4 + j;
                int rel = gj - q;
                bool ok = (rel >= -W_) && (rel <= W_) && smask[tg * 4 + j];
                sv[j] = ok ? s[i][j] : -1e9f;
                cm = fmaxf(cm, sv[j]);
            }
#pragma unroll
            for (int o = 1; o < 16; o <<= 1) cm = fmaxf(cm, __shfl_xor_sync(0xffffffffu, cm, o));
            float mn = fmaxf(m[i], cm);
            float alpha = __expf(m[i] - mn);
            float rs = 0.f;
#pragma unroll
            for (int j = 0; j < 4; j++) {
                float p = __expf(sv[j] - mn);
                Ps[(qg * 4 + i) * AT_LDK + tg * 4 + j] = p;
                rs += p;
            }
#pragma unroll
            for (int o = 1; o < 16; o <<= 1) rs += __shfl_xor_sync(0xffffffffu, rs, o);
            l[i] = l[i] * alpha + rs;
            m[i] = mn;
#pragma unroll
            for (int j = 0; j < 4; j++) acc[i][j] *= alpha;
        }
        __syncthreads();  // Ps written; K reads done -> overwrite KVs with V

        // V chunk (natural layout, float4 rows)
        for (int idx = tid; idx < 1024; idx += 256) {
            int r = idx >> 4, c4 = (idx & 15) * 4;
            int gj = jb + r;
            float4 v4 = (gj >= 0 && gj < S_)
                        ? *(const float4*)(Vb + (long)gj * D_ + h * DH_ + c4)
                        : make_float4(0.f, 0.f, 0.f, 0.f);
            *(float4*)&KVs[r * AT_LDK + c4] = v4;
        }
        __syncthreads();

        // acc += P @ V  (tg = dim group)
        for (int kl = 0; kl < 64; kl++) {
            float4 vv = *(const float4*)&KVs[kl * AT_LDK + tg * 4];
            float p0 = Ps[(qg * 4 + 0) * AT_LDK + kl];
            float p1 = Ps[(qg * 4 + 1) * AT_LDK + kl];
            float p2 = Ps[(qg * 4 + 2) * AT_LDK + kl];
            float p3 = Ps[(qg * 4 + 3) * AT_LDK + kl];
            acc[0][0] = fmaf(p0, vv.x, acc[0][0]); acc[0][1] = fmaf(p0, vv.y, acc[0][1]);
            acc[0][2] = fmaf(p0, vv.z, acc[0][2]); acc[0][3] = fmaf(p0, vv.w, acc[0][3]);
            acc[1][0] = fmaf(p1, vv.x, acc[1][0]); acc[1][1] = fmaf(p1, vv.y, acc[1][1]);
            acc[1][2] = fmaf(p1, vv.z, acc[1][2]); acc[1][3] = fmaf(p1, vv.w, acc[1][3]);
            acc[2][0] = fmaf(p2, vv.x, acc[2][0]); acc[2][1] = fmaf(p2, vv.y, acc[2][1]);
            acc[2][2] = fmaf(p2, vv.z, acc[2][2]); acc[2][3] = fmaf(p2, vv.w, acc[2][3]);
            acc[3][0] = fmaf(p3, vv.x, acc[3][0]); acc[3][1] = fmaf(p3, vv.y, acc[3][1]);
            acc[3][2] = fmaf(p3, vv.z, acc[3][2]); acc[3][3] = fmaf(p3, vv.w, acc[3][3]);
        }
    }

    // normalize + bf16 split out
#pragma unroll
    for (int i = 0; i < 4; i++) {
        float inv = 1.0f / l[i];
#pragma unroll
        for (int j = 0; j < 4; j++) {
            long idx = (long)(q0 + qg * 4 + i) * D_ + h * DH_ + tg * 4 + j;
            bsplit(acc[i][j] * inv, ch[idx], cl[idx]);
        }
    }
}

// ---------------- pooled head -------------------------------------------------
__global__ void pool_kernel(const float* __restrict__ x, const float* __restrict__ Wp,
                            const float* __restrict__ bp, float* __restrict__ out) {
    __shared__ float x0[D_];
    int tid = threadIdx.x;  // 128
    for (int i = tid; i < D_; i += 128) x0[i] = x[i];
    __syncthreads();
    int e = blockIdx.x * 128 + tid;
    float acc = bp[e];
    for (int d = 0; d < D_; d++) acc = fmaf(x0[d], Wp[(long)d * D_ + e], acc);
    out[e] = tanhf(acc);
}

__global__ void copy_kernel(const float* __restrict__ in, float* __restrict__ out, int n) {
    int i = blockIdx.x * blockDim.x + threadIdx.x;
    if (i < n) out[i] = in[i];
}

// ---------------- launch -------------------------------------------------------
extern "C" void kernel_launch(void* const* d_in, const int* in_sizes, int n_in,
                              void* d_out, int out_size) {
    const int*   input_ids = (const int*)d_in[0];
    const int*   attn_mask = (const int*)d_in[1];
    const float* word_emb  = (const float*)d_in[2];
    const float* pos_emb   = (const float*)d_in[3];
    const float* type_emb  = (const float*)d_in[4];
    const float* emb_ln_s  = (const float*)d_in[5];
    const float* emb_ln_b  = (const float*)d_in[6];
    const float* Wqkv      = (const float*)d_in[7];
    const float* bqkv      = (const float*)d_in[8];
    const float* Wo        = (const float*)d_in[9];
    const float* bo        = (const float*)d_in[10];
    const float* ln1_s     = (const float*)d_in[11];
    const float* ln1_b     = (const float*)d_in[12];
    const float* W1        = (const float*)d_in[13];
    const float* b1        = (const float*)d_in[14];
    const float* W2        = (const float*)d_in[15];
    const float* b2        = (const float*)d_in[16];
    const float* ln2_s     = (const float*)d_in[17];
    const float* ln2_b     = (const float*)d_in[18];
    const float* pool_W    = (const float*)d_in[19];
    const float* pool_b    = (const float*)d_in[20];
    float* out = (float*)d_out;

    float *x, *qkv, *y;
    int* pos;
    __nv_bfloat16 *xh, *xl, *ch, *cl, *hh, *hl;
    __nv_bfloat16 *wqh, *wql, *woh, *wol, *w1h, *w1l, *w2h, *w2l;
    cudaGetSymbolAddress((void**)&x, g_x);
    cudaGetSymbolAddress((void**)&qkv, g_qkv);
    cudaGetSymbolAddress((void**)&y, g_y);
    cudaGetSymbolAddress((void**)&pos, g_pos);
    cudaGetSymbolAddress((void**)&xh, g_xh); cudaGetSymbolAddress((void**)&xl, g_xl);
    cudaGetSymbolAddress((void**)&ch, g_ch); cudaGetSymbolAddress((void**)&cl, g_cl);
    cudaGetSymbolAddress((void**)&hh, g_hh); cudaGetSymbolAddress((void**)&hl, g_hl);
    cudaGetSymbolAddress((void**)&wqh, g_wqkv_h); cudaGetSymbolAddress((void**)&wql, g_wqkv_l);
    cudaGetSymbolAddress((void**)&woh, g_wo_h);   cudaGetSymbolAddress((void**)&wol, g_wo_l);
    cudaGetSymbolAddress((void**)&w1h, g_w1_h);   cudaGetSymbolAddress((void**)&w1l, g_w1_l);
    cudaGetSymbolAddress((void**)&w2h, g_w2_h);   cudaGetSymbolAddress((void**)&w2l, g_w2_l);

    cudaFuncSetAttribute(tgemm_kernel, cudaFuncAttributeMaxDynamicSharedMemorySize, GEMM_SMEM);
    cudaFuncSetAttribute(attn_fused_kernel, cudaFuncAttributeMaxDynamicSharedMemorySize, ATTN_SMEM);

    // order arranged so launch #6 (ncu -s 5 -c 1) is the QKV tgemm
    pos_kernel<<<1, 256>>>(attn_mask, pos);                                          // 1
    embed_ln_kernel<<<S_, 256>>>(input_ids, pos, word_emb, pos_emb, type_emb,
                                 emb_ln_s, emb_ln_b, x, xh, xl);                     // 2
    split_plain_kernel<<<(L_ * D_ * F_) / 256, 256>>>(W1, w1h, w1l);                 // 3
    split_plain_kernel<<<(L_ * F_ * D_) / 256, 256>>>(W2, w2h, w2l);                 // 4
    split_qkv_kernel<<<(L_ * 3 * D_ * D_) / 256, 256>>>(Wqkv, wqh, wql);             // 5

    for (int l = 0; l < L_; l++) {
        // fused QKV projection (N = 2304, qkv-remap epilogue)   (launch 6 on l=0)
        tgemm_kernel<<<dim3(QKV_N / BN, S_ / BM), 256, GEMM_SMEM>>>(
            xh, xl, wqh + (long)l * D_ * QKV_N, wql + (long)l * D_ * QKV_N,
            bqkv + (long)l * QKV_N, nullptr, qkv, nullptr, nullptr,
            S_, QKV_N, D_, 2);
        // fused banded flash attention
        attn_fused_kernel<<<dim3(S_ / 64, H_), 256, ATTN_SMEM>>>(qkv, attn_mask, ch, cl);
        if (l == 0)
            split_plain_kernel<<<(L_ * D_ * D_) / 256, 256>>>(Wo, woh, wol);
        // output projection + residual -> LN
        tgemm_kernel<<<dim3(D_ / BN, S_ / BM), 256, GEMM_SMEM>>>(
            ch, cl, woh + (long)l * D_ * D_, wol + (long)l * D_ * D_,
            bo + (long)l * D_, x, y, nullptr, nullptr, S_, D_, D_, 0);
        ln_kernel<<<S_, 256>>>(y, ln1_s + (long)l * D_, ln1_b + (long)l * D_, x, xh, xl);
        // FFN: W1 (gelu -> bf16 split), W2 (+resid) -> LN
        tgemm_kernel<<<dim3(F_ / BN, S_ / BM), 256, GEMM_SMEM>>>(
            xh, xl, w1h + (long)l * D_ * F_, w1l + (long)l * D_ * F_,
            b1 + (long)l * F_, nullptr, nullptr, hh, hl, S_, F_, D_, 1);
        tgemm_kernel<<<dim3(D_ / BN, S_ / BM), 256, GEMM_SMEM>>>(
            hh, hl, w2h + (long)l * F_ * D_, w2l + (long)l * F_ * D_,
            b2 + (long)l * D_, x, y, nullptr, nullptr, S_, D_, F_, 0);
        ln_kernel<<<S_, 256>>>(y, ln2_s + (long)l * D_, ln2_b + (long)l * D_, x, xh, xl);
    }

    copy_kernel<<<(S_ * D_ + 255) / 256, 256>>>(x, out, S_ * D_);
    pool_kernel<<<D_ / 128, 128>>>(x, pool_W, pool_b, out + (long)S_ * D_);
}

// round 16
// speedup vs baseline: 4.0290x; 1.1276x over previous
#include <cuda_runtime.h>
#include <cuda_bf16.h>
#include <math.h>
#include <stdint.h>
#include <mma.h>

using namespace nvcuda;

#define S_ 2048
#define D_ 768
#define H_ 12
#define DH_ 64
#define F_ 3072
#define L_ 2
#define W_ 256
#define QKV_N 2304   // packed q|k|v output width

// ---------------- scratch (static device memory; no allocations) -------------
__device__ float g_x[S_ * D_];            // residual stream (fp32)
__device__ float g_qkv[3 * S_ * D_];      // q/k/v fp32, each [s][h*64+dh]
__device__ float g_ys[3 * S_ * D_];       // split-K partial outputs
__device__ int   g_pos[S_];

// bf16 hi/lo activation splits (GEMM inputs)
__device__ __nv_bfloat16 g_xh[S_ * D_], g_xl[S_ * D_];
__device__ __nv_bfloat16 g_ch[S_ * D_], g_cl[S_ * D_];
__device__ __nv_bfloat16 g_hh[S_ * F_], g_hl[S_ * F_];

// bf16 hi/lo weight splits, [K][N] layout (built once per launch)
__device__ __nv_bfloat16 g_wqkv_h[L_ * D_ * QKV_N], g_wqkv_l[L_ * D_ * QKV_N];
__device__ __nv_bfloat16 g_wo_h[L_ * D_ * D_],      g_wo_l[L_ * D_ * D_];
__device__ __nv_bfloat16 g_w1_h[L_ * D_ * F_],      g_w1_l[L_ * D_ * F_];
__device__ __nv_bfloat16 g_w2_h[L_ * F_ * D_],      g_w2_l[L_ * F_ * D_];

// ---------------- helpers -----------------------------------------------------
__device__ __forceinline__ void bsplit(float v, __nv_bfloat16& hi, __nv_bfloat16& lo) {
    hi = __float2bfloat16(v);
    lo = __float2bfloat16(v - __bfloat162float(hi));
}

__device__ __forceinline__ void cpasync16(unsigned int dst, const void* src) {
    asm volatile("cp.async.cg.shared.global [%0], [%1], 16;" :: "r"(dst), "l"(src));
}
__device__ __forceinline__ void cp_commit() { asm volatile("cp.async.commit_group;"); }
__device__ __forceinline__ void cp_wait1()  { asm volatile("cp.async.wait_group 1;"); }

template <int NT>
__device__ __forceinline__ float blkSum(float v, float* red) {
    int tid = threadIdx.x;
    red[tid] = v; __syncthreads();
#pragma unroll
    for (int s = NT / 2; s > 0; s >>= 1) {
        if (tid < s) red[tid] += red[tid + s];
        __syncthreads();
    }
    float r = red[0]; __syncthreads();
    return r;
}

// ---------------- weight split kernels ----------------------------------------
// Wqkv [L][3][D][D] -> per-layer packed [K=D][N=3D] with n = t*D + e
__global__ void split_qkv_kernel(const float* __restrict__ src,
                                 __nv_bfloat16* __restrict__ hi, __nv_bfloat16* __restrict__ lo) {
    long i = (long)blockIdx.x * 256 + threadIdx.x;
    int e = i % D_;
    int d = (i / D_) % D_;
    int t = (i / ((long)D_ * D_)) % 3;
    int l = i / (3l * D_ * D_);
    long dst = (long)l * D_ * QKV_N + (long)d * QKV_N + t * D_ + e;
    bsplit(src[i], hi[dst], lo[dst]);
}

__global__ void split_plain_kernel(const float* __restrict__ src,
                                   __nv_bfloat16* __restrict__ hi, __nv_bfloat16* __restrict__ lo) {
    long i = (long)blockIdx.x * 256 + threadIdx.x;
    bsplit(src[i], hi[i], lo[i]);
}

// ---------------- pos ids ------------------------------------------------------
__global__ void pos_kernel(const int* __restrict__ mask, int* __restrict__ pos) {
    __shared__ int part[257];
    int tid = threadIdx.x;
    int c[8];
    int acc = 0;
#pragma unroll
    for (int i = 0; i < 8; i++) { acc += mask[tid * 8 + i]; c[i] = acc; }
    part[tid + 1] = acc;
    __syncthreads();
    if (tid == 0) {
        part[0] = 0;
        for (int i = 1; i <= 256; i++) part[i] += part[i - 1];
    }
    __syncthreads();
    int base = part[tid];
#pragma unroll
    for (int i = 0; i < 8; i++) {
        int idx = tid * 8 + i;
        pos[idx] = (base + c[i]) * mask[idx] + 1;
    }
}

// ---------------- embedding + LayerNorm ---------------------------------------
__global__ void embed_ln_kernel(const int* __restrict__ ids, const int* __restrict__ pos,
                                const float* __restrict__ we, const float* __restrict__ pe,
                                const float* __restrict__ te,
                                const float* __restrict__ gs, const float* __restrict__ gb,
                                float* __restrict__ out,
                                __nv_bfloat16* __restrict__ oh, __nv_bfloat16* __restrict__ ol) {
    int row = blockIdx.x;
    int tid = threadIdx.x;
    __shared__ float buf[D_];
    __shared__ float red[256];
    const float* w = we + (long)ids[row] * D_;
    const float* p = pe + (long)pos[row] * D_;
    float lsum = 0.f, lsq = 0.f;
#pragma unroll
    for (int i = 0; i < 3; i++) {
        int d = tid + i * 256;
        float v = w[d] + p[d] + te[d];
        buf[d] = v;
        lsum += v; lsq += v * v;
    }
    float total = blkSum<256>(lsum, red);
    float totsq = blkSum<256>(lsq, red);
    float mean = total * (1.f / D_);
    float var  = totsq * (1.f / D_) - mean * mean;
    float inv  = rsqrtf(var + 1e-5f);
#pragma unroll
    for (int i = 0; i < 3; i++) {
        int d = tid + i * 256;
        float v = (buf[d] - mean) * inv * gs[d] + gb[d];
        long idx = (long)row * D_ + d;
        out[idx] = v;
        bsplit(v, oh[idx], ol[idx]);
    }
}

// ---------------- LayerNorm over sum of 3 split-K partials ---------------------
__global__ void ln3_kernel(const float* __restrict__ ys,
                           const float* __restrict__ gs, const float* __restrict__ gb,
                           float* __restrict__ out,
                           __nv_bfloat16* __restrict__ oh, __nv_bfloat16* __restrict__ ol) {
    int row = blockIdx.x;
    int tid = threadIdx.x;
    __shared__ float red[256];
    const float* r0 = ys + (long)row * D_;
    const float* r1 = r0 + (long)S_ * D_;
    const float* r2 = r0 + 2l * S_ * D_;
    float v[3];
    float lsum = 0.f, lsq = 0.f;
#pragma unroll
    for (int i = 0; i < 3; i++) {
        int d = tid + i * 256;
        float t = r0[d] + r1[d] + r2[d];
        v[i] = t;
        lsum += t; lsq += t * t;
    }
    float total = blkSum<256>(lsum, red);
    float totsq = blkSum<256>(lsq, red);
    float mean = total * (1.f / D_);
    float var  = totsq * (1.f / D_) - mean * mean;
    float inv  = rsqrtf(var + 1e-5f);
#pragma unroll
    for (int i = 0; i < 3; i++) {
        int d = tid + i * 256;
        float o = (v[i] - mean) * inv * gs[d] + gb[d];
        long idx = (long)row * D_ + d;
        out[idx] = o;
        bsplit(o, oh[idx], ol[idx]);
    }
}

// ---------------- bf16-split tensor-core GEMM ---------------------------------
// C = epilogue(A @ B + bias). A=[M][K] (Ah+Al), B=[K][N] (Bh+Bl), 3 MMAs per k16.
// modes: 0 fp32 out (+resid); 1 gelu->bf16 split; 2 qkv remap; 3 split-K partial
//        (gridDim.z slices; kz=0 adds bias+resid; C + kz*S*D)
#define BM 128
#define BN 128
#define BKq 32
#define LDA_ 40
#define LDB_ 136
#define ASTG (BM * LDA_)
#define BSTG (BKq * LDB_)
#define STG_ELE (2 * ASTG + 2 * BSTG)
#define STG_BYTES (STG_ELE * 2)
#define GEMM_SMEM (2 * STG_BYTES)

__device__ __forceinline__ void load_stage(
    unsigned int sb,
    const __nv_bfloat16* __restrict__ Ah, const __nv_bfloat16* __restrict__ Al,
    const __nv_bfloat16* __restrict__ Bh, const __nv_bfloat16* __restrict__ Bl,
    int bRow, int bCol, int arow, int akc, int brow, int bcol,
    int k0, int N, int K)
{
    const __nv_bfloat16* gah = Ah + (long)(bRow + arow) * K + k0 + akc;
    const __nv_bfloat16* gal = Al + (long)(bRow + arow) * K + k0 + akc;
    cpasync16(sb + (arow * LDA_ + akc) * 2, gah);
    cpasync16(sb + ((arow + 64) * LDA_ + akc) * 2, gah + 64l * K);
    cpasync16(sb + ASTG * 2 + (arow * LDA_ + akc) * 2, gal);
    cpasync16(sb + ASTG * 2 + ((arow + 64) * LDA_ + akc) * 2, gal + 64l * K);
    const __nv_bfloat16* gbh = Bh + (long)(k0 + brow) * N + bCol + bcol;
    const __nv_bfloat16* gbl = Bl + (long)(k0 + brow) * N + bCol + bcol;
    cpasync16(sb + 2 * ASTG * 2 + (brow * LDB_ + bcol) * 2, gbh);
    cpasync16(sb + 2 * ASTG * 2 + ((brow + 16) * LDB_ + bcol) * 2, gbh + 16l * N);
    cpasync16(sb + (2 * ASTG + BSTG) * 2 + (brow * LDB_ + bcol) * 2, gbl);
    cpasync16(sb + (2 * ASTG + BSTG) * 2 + ((brow + 16) * LDB_ + bcol) * 2, gbl + 16l * N);
}

__global__ __launch_bounds__(256, 2)
void tgemm_kernel(const __nv_bfloat16* __restrict__ Ah, const __nv_bfloat16* __restrict__ Al,
                  const __nv_bfloat16* __restrict__ Bh, const __nv_bfloat16* __restrict__ Bl,
                  const float* __restrict__ bias, const float* __restrict__ resid,
                  float* __restrict__ C,
                  __nv_bfloat16* __restrict__ Ch, __nv_bfloat16* __restrict__ Cl,
                  int M, int N, int K, int Klen, int mode) {
    extern __shared__ __nv_bfloat16 smem[];
    const int tid  = threadIdx.x;
    const int lane = tid & 31;
    const int wid  = tid >> 5;
    const int wr   = wid >> 2;
    const int wc   = wid & 3;
    const int bRow = blockIdx.y * BM;
    const int bCol = blockIdx.x * BN;
    const int kz   = blockIdx.z;
    const int koff = kz * Klen;

    const int arow = tid >> 2;
    const int akc  = (tid & 3) * 8;
    const int brow = tid >> 4;
    const int bcol = (tid & 15) * 8;

    const unsigned int smem_u = (unsigned int)__cvta_generic_to_shared(smem);

    wmma::fragment<wmma::accumulator, 16, 16, 16, float> acc[4][2];
#pragma unroll
    for (int i = 0; i < 4; i++)
#pragma unroll
        for (int j = 0; j < 2; j++) wmma::fill_fragment(acc[i][j], 0.0f);

    const int nt = Klen / BKq;

    load_stage(smem_u, Ah, Al, Bh, Bl, bRow, bCol, arow, akc, brow, bcol, koff, N, K);
    cp_commit();

    for (int t = 0; t < nt; t++) {
        if (t + 1 < nt)
            load_stage(smem_u + ((t + 1) & 1) * STG_BYTES, Ah, Al, Bh, Bl,
                       bRow, bCol, arow, akc, brow, bcol, koff + (t + 1) * BKq, N, K);
        cp_commit();
        cp_wait1();
        __syncthreads();

        const __nv_bfloat16* base = smem + (t & 1) * STG_ELE;
#pragma unroll
        for (int ks = 0; ks < BKq; ks += 16) {
            wmma::fragment<wmma::matrix_a, 16, 16, 16, __nv_bfloat16, wmma::row_major> ah[4], al[4];
#pragma unroll
            for (int i = 0; i < 4; i++) {
                wmma::load_matrix_sync(ah[i], base + (wr * 64 + i * 16) * LDA_ + ks, LDA_);
                wmma::load_matrix_sync(al[i], base + ASTG + (wr * 64 + i * 16) * LDA_ + ks, LDA_);
            }
#pragma unroll
            for (int j = 0; j < 2; j++) {
                wmma::fragment<wmma::matrix_b, 16, 16, 16, __nv_bfloat16, wmma::row_major> bh, bl;
                wmma::load_matrix_sync(bh, base + 2 * ASTG + ks * LDB_ + wc * 32 + j * 16, LDB_);
                wmma::load_matrix_sync(bl, base + 2 * ASTG + BSTG + ks * LDB_ + wc * 32 + j * 16, LDB_);
                // term-outer ordering: dependent reuse distance per acc = 4 MMAs
#pragma unroll
                for (int i = 0; i < 4; i++)
                    wmma::mma_sync(acc[i][j], ah[i], bl, acc[i][j]);
#pragma unroll
                for (int i = 0; i < 4; i++)
                    wmma::mma_sync(acc[i][j], al[i], bh, acc[i][j]);
#pragma unroll
                for (int i = 0; i < 4; i++)
                    wmma::mma_sync(acc[i][j], ah[i], bh, acc[i][j]);
            }
        }
        __syncthreads();
    }

    // epilogue: per-warp staging through (reused) smem
    float* ws = (float*)smem + wid * (16 * 36);
    const int gc = bCol + wc * 32 + lane;
#pragma unroll
    for (int mi = 0; mi < 4; mi++) {
        wmma::store_matrix_sync(ws,      acc[mi][0], 36, wmma::mem_row_major);
        wmma::store_matrix_sync(ws + 16, acc[mi][1], 36, wmma::mem_row_major);
        __syncwarp();
        const int gr0 = bRow + wr * 64 + mi * 16;
#pragma unroll
        for (int r = 0; r < 16; r++) {
            float v = ws[r * 36 + lane];
            long idx = (long)(gr0 + r) * N + gc;
            if (mode == 0) {
                v += bias[gc];
                if (resid) v += resid[idx];
                C[idx] = v;
            } else if (mode == 1) {
                v += bias[gc];
                v = 0.5f * v * (1.0f + erff(v * 0.70710678118654752f));
                bsplit(v, Ch[idx], Cl[idx]);
            } else if (mode == 2) {  // packed qkv -> [t][s][e]
                v += bias[gc];
                int tq = gc / D_;
                C[(long)tq * S_ * D_ + (long)(gr0 + r) * D_ + (gc - tq * D_)] = v;
            } else {  // mode 3: split-K partial
                if (kz == 0) { v += bias[gc]; v += resid[idx]; }
                C[(long)kz * S_ * D_ + idx] = v;
            }
        }
        __syncwarp();
    }
}

// ---------------- fused banded flash attention --------------------------------
#define AT_LDQ 65
#define AT_LDK 68
#define ATTN_SMEM ((64 * AT_LDQ + 2 * 64 * AT_LDK) * 4)

__global__ __launch_bounds__(256)
void attn_fused_kernel(const float* __restrict__ qkv, const int* __restrict__ mask,
                       __nv_bfloat16* __restrict__ ch, __nv_bfloat16* __restrict__ cl) {
    extern __shared__ float asm_[];
    float* Qs  = asm_;
    float* KVs = asm_ + 64 * AT_LDQ;
    float* Ps  = KVs + 64 * AT_LDK;
    __shared__ int smask[64];

    const int q0  = blockIdx.x * 64;
    const int h   = blockIdx.y;
    const int tid = threadIdx.x;
    const int qg  = tid >> 4;
    const int tg  = tid & 15;

    const float* Qb = qkv;
    const float* Kb = qkv + (long)S_ * D_;
    const float* Vb = qkv + 2l * S_ * D_;

    for (int idx = tid; idx < 4096; idx += 256) {
        int r = idx >> 6, c = idx & 63;
        Qs[r * AT_LDQ + c] = Qb[(long)(q0 + r) * D_ + h * DH_ + c] * 0.125f;
    }

    float m[4], l[4], acc[4][4];
#pragma unroll
    for (int i = 0; i < 4; i++) {
        m[i] = -1e30f; l[i] = 0.f;
#pragma unroll
        for (int j = 0; j < 4; j++) acc[i][j] = 0.f;
    }

    for (int c9 = 0; c9 < 9; c9++) {
        const int jb = q0 - W_ + c9 * 64;
        __syncthreads();
        {
            int j  = tid & 63;
            int gj = jb + j;
            bool ok = (gj >= 0 && gj < S_);
            const float* kr = Kb + (long)gj * D_ + h * DH_;
            for (int d4 = (tid >> 6) * 4; d4 < 64; d4 += 16) {
                float4 k4 = ok ? *(const float4*)(kr + d4) : make_float4(0.f, 0.f, 0.f, 0.f);
                KVs[(d4 + 0) * AT_LDK + j] = k4.x;
                KVs[(d4 + 1) * AT_LDK + j] = k4.y;
                KVs[(d4 + 2) * AT_LDK + j] = k4.z;
                KVs[(d4 + 3) * AT_LDK + j] = k4.w;
            }
            if (tid < 64) smask[tid] = (jb + tid >= 0 && jb + tid < S_) ? mask[jb + tid] : 0;
        }
        __syncthreads();

        float s[4][4];
#pragma unroll
        for (int i = 0; i < 4; i++)
#pragma unroll
            for (int j = 0; j < 4; j++) s[i][j] = 0.f;
        for (int d = 0; d < 64; d++) {
            float4 kv = *(const float4*)&KVs[d * AT_LDK + tg * 4];
            float q0v = Qs[(qg * 4 + 0) * AT_LDQ + d];
            float q1v = Qs[(qg * 4 + 1) * AT_LDQ + d];
            float q2v = Qs[(qg * 4 + 2) * AT_LDQ + d];
            float q3v = Qs[(qg * 4 + 3) * AT_LDQ + d];
            s[0][0] = fmaf(q0v, kv.x, s[0][0]); s[0][1] = fmaf(q0v, kv.y, s[0][1]);
            s[0][2] = fmaf(q0v, kv.z, s[0][2]); s[0][3] = fmaf(q0v, kv.w, s[0][3]);
            s[1][0] = fmaf(q1v, kv.x, s[1][0]); s[1][1] = fmaf(q1v, kv.y, s[1][1]);
            s[1][2] = fmaf(q1v, kv.z, s[1][2]); s[1][3] = fmaf(q1v, kv.w, s[1][3]);
            s[2][0] = fmaf(q2v, kv.x, s[2][0]); s[2][1] = fmaf(q2v, kv.y, s[2][1]);
            s[2][2] = fmaf(q2v, kv.z, s[2][2]); s[2][3] = fmaf(q2v, kv.w, s[2][3]);
            s[3][0] = fmaf(q3v, kv.x, s[3][0]); s[3][1] = fmaf(q3v, kv.y, s[3][1]);
            s[3][2] = fmaf(q3v, kv.z, s[3][2]); s[3][3] = fmaf(q3v, kv.w, s[3][3]);
        }

#pragma unroll
        for (int i = 0; i < 4; i++) {
            int q = q0 + qg * 4 + i;
            float sv[4];
            float cm = -1e30f;
#pragma unroll
            for (int j = 0; j < 4; j++) {
                int gj = jb + tg * 4 + j;
                int rel = gj - q;
                bool ok = (rel >= -W_) && (rel <= W_) && smask[tg * 4 + j];
                sv[j] = ok ? s[i][j] : -1e9f;
                cm = fmaxf(cm, sv[j]);
            }
#pragma unroll
            for (int o = 1; o < 16; o <<= 1) cm = fmaxf(cm, __shfl_xor_sync(0xffffffffu, cm, o));
            float mn = fmaxf(m[i], cm);
            float alpha = __expf(m[i] - mn);
            float rs = 0.f;
#pragma unroll
            for (int j = 0; j < 4; j++) {
                float p = __expf(sv[j] - mn);
                Ps[(qg * 4 + i) * AT_LDK + tg * 4 + j] = p;
                rs += p;
            }
#pragma unroll
            for (int o = 1; o < 16; o <<= 1) rs += __shfl_xor_sync(0xffffffffu, rs, o);
            l[i] = l[i] * alpha + rs;
            m[i] = mn;
#pragma unroll
            for (int j = 0; j < 4; j++) acc[i][j] *= alpha;
        }
        __syncthreads();

        for (int idx = tid; idx < 1024; idx += 256) {
            int r = idx >> 4, c4 = (idx & 15) * 4;
            int gj = jb + r;
            float4 v4 = (gj >= 0 && gj < S_)
                        ? *(const float4*)(Vb + (long)gj * D_ + h * DH_ + c4)
                        : make_float4(0.f, 0.f, 0.f, 0.f);
            *(float4*)&KVs[r * AT_LDK + c4] = v4;
        }
        __syncthreads();

        for (int kl = 0; kl < 64; kl++) {
            float4 vv = *(const float4*)&KVs[kl * AT_LDK + tg * 4];
            float p0 = Ps[(qg * 4 + 0) * AT_LDK + kl];
            float p1 = Ps[(qg * 4 + 1) * AT_LDK + kl];
            float p2 = Ps[(qg * 4 + 2) * AT_LDK + kl];
            float p3 = Ps[(qg * 4 + 3) * AT_LDK + kl];
            acc[0][0] = fmaf(p0, vv.x, acc[0][0]); acc[0][1] = fmaf(p0, vv.y, acc[0][1]);
            acc[0][2] = fmaf(p0, vv.z, acc[0][2]); acc[0][3] = fmaf(p0, vv.w, acc[0][3]);
            acc[1][0] = fmaf(p1, vv.x, acc[1][0]); acc[1][1] = fmaf(p1, vv.y, acc[1][1]);
            acc[1][2] = fmaf(p1, vv.z, acc[1][2]); acc[1][3] = fmaf(p1, vv.w, acc[1][3]);
            acc[2][0] = fmaf(p2, vv.x, acc[2][0]); acc[2][1] = fmaf(p2, vv.y, acc[2][1]);
            acc[2][2] = fmaf(p2, vv.z, acc[2][2]); acc[2][3] = fmaf(p2, vv.w, acc[2][3]);
            acc[3][0] = fmaf(p3, vv.x, acc[3][0]); acc[3][1] = fmaf(p3, vv.y, acc[3][1]);
            acc[3][2] = fmaf(p3, vv.z, acc[3][2]); acc[3][3] = fmaf(p3, vv.w, acc[3][3]);
        }
    }

#pragma unroll
    for (int i = 0; i < 4; i++) {
        float inv = 1.0f / l[i];
#pragma unroll
        for (int j = 0; j < 4; j++) {
            long idx = (long)(q0 + qg * 4 + i) * D_ + h * DH_ + tg * 4 + j;
            bsplit(acc[i][j] * inv, ch[idx], cl[idx]);
        }
    }
}

// ---------------- pooled head --------------------------------------------------
__global__ void pool_kernel(const float* __restrict__ x, const float* __restrict__ Wp,
                            const float* __restrict__ bp, float* __restrict__ out) {
    __shared__ float x0[D_];
    int tid = threadIdx.x;
    for (int i = tid; i < D_; i += 128) x0[i] = x[i];
    __syncthreads();
    int e = blockIdx.x * 128 + tid;
    float acc = bp[e];
    for (int d = 0; d < D_; d++) acc = fmaf(x0[d], Wp[(long)d * D_ + e], acc);
    out[e] = tanhf(acc);
}

__global__ void copy_kernel(const float* __restrict__ in, float* __restrict__ out, int n) {
    int i = blockIdx.x * blockDim.x + threadIdx.x;
    if (i < n) out[i] = in[i];
}

// ---------------- launch --------------------------------------------------------
extern "C" void kernel_launch(void* const* d_in, const int* in_sizes, int n_in,
                              void* d_out, int out_size) {
    const int*   input_ids = (const int*)d_in[0];
    const int*   attn_mask = (const int*)d_in[1];
    const float* word_emb  = (const float*)d_in[2];
    const float* pos_emb   = (const float*)d_in[3];
    const float* type_emb  = (const float*)d_in[4];
    const float* emb_ln_s  = (const float*)d_in[5];
    const float* emb_ln_b  = (const float*)d_in[6];
    const float* Wqkv      = (const float*)d_in[7];
    const float* bqkv      = (const float*)d_in[8];
    const float* Wo        = (const float*)d_in[9];
    const float* bo        = (const float*)d_in[10];
    const float* ln1_s     = (const float*)d_in[11];
    const float* ln1_b     = (const float*)d_in[12];
    const float* W1        = (const float*)d_in[13];
    const float* b1        = (const float*)d_in[14];
    const float* W2        = (const float*)d_in[15];
    const float* b2        = (const float*)d_in[16];
    const float* ln2_s     = (const float*)d_in[17];
    const float* ln2_b     = (const float*)d_in[18];
    const float* pool_W    = (const float*)d_in[19];
    const float* pool_b    = (const float*)d_in[20];
    float* out = (float*)d_out;

    float *x, *qkv, *ys;
    int* pos;
    __nv_bfloat16 *xh, *xl, *ch, *cl, *hh, *hl;
    __nv_bfloat16 *wqh, *wql, *woh, *wol, *w1h, *w1l, *w2h, *w2l;
    cudaGetSymbolAddress((void**)&x, g_x);
    cudaGetSymbolAddress((void**)&qkv, g_qkv);
    cudaGetSymbolAddress((void**)&ys, g_ys);
    cudaGetSymbolAddress((void**)&pos, g_pos);
    cudaGetSymbolAddress((void**)&xh, g_xh); cudaGetSymbolAddress((void**)&xl, g_xl);
    cudaGetSymbolAddress((void**)&ch, g_ch); cudaGetSymbolAddress((void**)&cl, g_cl);
    cudaGetSymbolAddress((void**)&hh, g_hh); cudaGetSymbolAddress((void**)&hl, g_hl);
    cudaGetSymbolAddress((void**)&wqh, g_wqkv_h); cudaGetSymbolAddress((void**)&wql, g_wqkv_l);
    cudaGetSymbolAddress((void**)&woh, g_wo_h);   cudaGetSymbolAddress((void**)&wol, g_wo_l);
    cudaGetSymbolAddress((void**)&w1h, g_w1_h);   cudaGetSymbolAddress((void**)&w1l, g_w1_l);
    cudaGetSymbolAddress((void**)&w2h, g_w2_h);   cudaGetSymbolAddress((void**)&w2l, g_w2_l);

    cudaFuncSetAttribute(tgemm_kernel, cudaFuncAttributeMaxDynamicSharedMemorySize, GEMM_SMEM);
    cudaFuncSetAttribute(attn_fused_kernel, cudaFuncAttributeMaxDynamicSharedMemorySize, ATTN_SMEM);

    pos_kernel<<<1, 256>>>(attn_mask, pos);
    embed_ln_kernel<<<S_, 256>>>(input_ids, pos, word_emb, pos_emb, type_emb,
                                 emb_ln_s, emb_ln_b, x, xh, xl);
    split_plain_kernel<<<(L_ * D_ * F_) / 256, 256>>>(W1, w1h, w1l);
    split_plain_kernel<<<(L_ * F_ * D_) / 256, 256>>>(W2, w2h, w2l);
    split_qkv_kernel<<<(L_ * 3 * D_ * D_) / 256, 256>>>(Wqkv, wqh, wql);

    for (int l = 0; l < L_; l++) {
        // fused QKV projection (N = 2304, qkv-remap epilogue)
        tgemm_kernel<<<dim3(QKV_N / BN, S_ / BM, 1), 256, GEMM_SMEM>>>(
            xh, xl, wqh + (long)l * D_ * QKV_N, wql + (long)l * D_ * QKV_N,
            bqkv + (long)l * QKV_N, nullptr, qkv, nullptr, nullptr,
            S_, QKV_N, D_, D_, 2);
        // fused banded flash attention
        attn_fused_kernel<<<dim3(S_ / 64, H_), 256, ATTN_SMEM>>>(qkv, attn_mask, ch, cl);
        if (l == 0)
            split_plain_kernel<<<(L_ * D_ * D_) / 256, 256>>>(Wo, woh, wol);
        // output projection + residual (split-K=3) -> LN
        tgemm_kernel<<<dim3(D_ / BN, S_ / BM, 3), 256, GEMM_SMEM>>>(
            ch, cl, woh + (long)l * D_ * D_, wol + (long)l * D_ * D_,
            bo + (long)l * D_, x, ys, nullptr, nullptr, S_, D_, D_, D_ / 3, 3);
        ln3_kernel<<<S_, 256>>>(ys, ln1_s + (long)l * D_, ln1_b + (long)l * D_, x, xh, xl);
        // FFN: W1 (gelu -> bf16 split), W2 (split-K=3, +resid) -> LN
        tgemm_kernel<<<dim3(F_ / BN, S_ / BM, 1), 256, GEMM_SMEM>>>(
            xh, xl, w1h + (long)l * D_ * F_, w1l + (long)l * D_ * F_,
            b1 + (long)l * F_, nullptr, nullptr, hh, hl, S_, F_, D_, D_, 1);
        tgemm_kernel<<<dim3(D_ / BN, S_ / BM, 3), 256, GEMM_SMEM>>>(
            hh, hl, w2h + (long)l * F_ * D_, w2l + (long)l * F_ * D_,
            b2 + (long)l * D_, x, ys, nullptr, nullptr, S_, D_, F_, F_ / 3, 3);
        ln3_kernel<<<S_, 256>>>(ys, ln2_s + (long)l * D_, ln2_b + (long)l * D_, x, xh, xl);
    }

    copy_kernel<<<(S_ * D_ + 255) / 256, 256>>>(x, out, S_ * D_);
    pool_kernel<<<D_ / 128, 128>>>(x, pool_W, pool_b, out + (long)S_ * D_);
}

// round 17
// speedup vs baseline: 4.2128x; 1.0456x over previous
#include <cuda_runtime.h>
#include <cuda_fp16.h>
#include <math.h>
#include <stdint.h>
#include <mma.h>

using namespace nvcuda;

#define S_ 2048
#define D_ 768
#define H_ 12
#define DH_ 64
#define F_ 3072
#define L_ 2
#define W_ 256
#define QKV_N 2304   // packed q|k|v output width

// ---------------- scratch (static device memory; no allocations) -------------
__device__ float g_x[S_ * D_];            // residual stream (fp32)
__device__ float g_qkv[3 * S_ * D_];      // q/k/v fp32
__device__ float g_ys[3 * S_ * D_];       // split-K partial outputs
__device__ int   g_pos[S_];

// fp16 hi/lo activation splits (GEMM inputs)
__device__ __half g_xh[S_ * D_], g_xl[S_ * D_];
__device__ __half g_ch[S_ * D_], g_cl[S_ * D_];
__device__ __half g_hh[S_ * F_], g_hl[S_ * F_];

// fp16 hi/lo weight splits, [K][N] layout (built once per launch)
__device__ __half g_wqkv_h[L_ * D_ * QKV_N], g_wqkv_l[L_ * D_ * QKV_N];
__device__ __half g_wo_h[L_ * D_ * D_],      g_wo_l[L_ * D_ * D_];
__device__ __half g_w1_h[L_ * D_ * F_],      g_w1_l[L_ * D_ * F_];
__device__ __half g_w2_h[L_ * F_ * D_],      g_w2_l[L_ * F_ * D_];

// ---------------- helpers -----------------------------------------------------
__device__ __forceinline__ void hsplit(float v, __half& hi, __half& lo) {
    hi = __float2half_rn(v);
    lo = __float2half_rn(v - __half2float(hi));
}

__device__ __forceinline__ void cpasync16(unsigned int dst, const void* src) {
    asm volatile("cp.async.cg.shared.global [%0], [%1], 16;" :: "r"(dst), "l"(src));
}
__device__ __forceinline__ void cp_commit() { asm volatile("cp.async.commit_group;"); }
__device__ __forceinline__ void cp_wait1()  { asm volatile("cp.async.wait_group 1;"); }

template <int NT>
__device__ __forceinline__ float blkSum(float v, float* red) {
    int tid = threadIdx.x;
    red[tid] = v; __syncthreads();
#pragma unroll
    for (int s = NT / 2; s > 0; s >>= 1) {
        if (tid < s) red[tid] += red[tid + s];
        __syncthreads();
    }
    float r = red[0]; __syncthreads();
    return r;
}

// ---------------- weight split kernels (vectorized x4) -------------------------
// Wqkv [L][3][D][D] -> per-layer packed [K=D][N=3D]; 4 consecutive e contiguous
__global__ void split_qkv_kernel(const float* __restrict__ src,
                                 __half* __restrict__ hi, __half* __restrict__ lo) {
    long i4 = ((long)blockIdx.x * 256 + threadIdx.x) * 4;   // over L*3*D*D
    int e = i4 % D_;
    int d = (i4 / D_) % D_;
    int t = (i4 / ((long)D_ * D_)) % 3;
    int l = i4 / (3l * D_ * D_);
    long dst = (long)l * D_ * QKV_N + (long)d * QKV_N + t * D_ + e;
    float4 v = *(const float4*)(src + i4);
    __half h0, h1, h2, h3, l0, l1, l2, l3;
    hsplit(v.x, h0, l0); hsplit(v.y, h1, l1); hsplit(v.z, h2, l2); hsplit(v.w, h3, l3);
    *(__half2*)(hi + dst)     = __halves2half2(h0, h1);
    *(__half2*)(hi + dst + 2) = __halves2half2(h2, h3);
    *(__half2*)(lo + dst)     = __halves2half2(l0, l1);
    *(__half2*)(lo + dst + 2) = __halves2half2(l2, l3);
}

__global__ void split_plain_kernel(const float* __restrict__ src,
                                   __half* __restrict__ hi, __half* __restrict__ lo) {
    long i4 = ((long)blockIdx.x * 256 + threadIdx.x) * 4;
    float4 v = *(const float4*)(src + i4);
    __half h0, h1, h2, h3, l0, l1, l2, l3;
    hsplit(v.x, h0, l0); hsplit(v.y, h1, l1); hsplit(v.z, h2, l2); hsplit(v.w, h3, l3);
    *(__half2*)(hi + i4)     = __halves2half2(h0, h1);
    *(__half2*)(hi + i4 + 2) = __halves2half2(h2, h3);
    *(__half2*)(lo + i4)     = __halves2half2(l0, l1);
    *(__half2*)(lo + i4 + 2) = __halves2half2(l2, l3);
}

// ---------------- pos ids ------------------------------------------------------
__global__ void pos_kernel(const int* __restrict__ mask, int* __restrict__ pos) {
    __shared__ int part[257];
    int tid = threadIdx.x;
    int c[8];
    int acc = 0;
#pragma unroll
    for (int i = 0; i < 8; i++) { acc += mask[tid * 8 + i]; c[i] = acc; }
    part[tid + 1] = acc;
    __syncthreads();
    if (tid == 0) {
        part[0] = 0;
        for (int i = 1; i <= 256; i++) part[i] += part[i - 1];
    }
    __syncthreads();
    int base = part[tid];
#pragma unroll
    for (int i = 0; i < 8; i++) {
        int idx = tid * 8 + i;
        pos[idx] = (base + c[i]) * mask[idx] + 1;
    }
}

// ---------------- embedding + LayerNorm ---------------------------------------
__global__ void embed_ln_kernel(const int* __restrict__ ids, const int* __restrict__ pos,
                                const float* __restrict__ we, const float* __restrict__ pe,
                                const float* __restrict__ te,
                                const float* __restrict__ gs, const float* __restrict__ gb,
                                float* __restrict__ out,
                                __half* __restrict__ oh, __half* __restrict__ ol) {
    int row = blockIdx.x;
    int tid = threadIdx.x;
    __shared__ float buf[D_];
    __shared__ float red[256];
    const float* w = we + (long)ids[row] * D_;
    const float* p = pe + (long)pos[row] * D_;
    float lsum = 0.f, lsq = 0.f;
#pragma unroll
    for (int i = 0; i < 3; i++) {
        int d = tid + i * 256;
        float v = w[d] + p[d] + te[d];
        buf[d] = v;
        lsum += v; lsq += v * v;
    }
    float total = blkSum<256>(lsum, red);
    float totsq = blkSum<256>(lsq, red);
    float mean = total * (1.f / D_);
    float var  = totsq * (1.f / D_) - mean * mean;
    float inv  = rsqrtf(var + 1e-5f);
#pragma unroll
    for (int i = 0; i < 3; i++) {
        int d = tid + i * 256;
        float v = (buf[d] - mean) * inv * gs[d] + gb[d];
        long idx = (long)row * D_ + d;
        out[idx] = v;
        hsplit(v, oh[idx], ol[idx]);
    }
}

// ---------------- LayerNorm over sum of 3 split-K partials ---------------------
__global__ void ln3_kernel(const float* __restrict__ ys,
                           const float* __restrict__ gs, const float* __restrict__ gb,
                           float* __restrict__ out,
                           __half* __restrict__ oh, __half* __restrict__ ol) {
    int row = blockIdx.x;
    int tid = threadIdx.x;
    __shared__ float red[256];
    const float* r0 = ys + (long)row * D_;
    const float* r1 = r0 + (long)S_ * D_;
    const float* r2 = r0 + 2l * S_ * D_;
    float v[3];
    float lsum = 0.f, lsq = 0.f;
#pragma unroll
    for (int i = 0; i < 3; i++) {
        int d = tid + i * 256;
        float t = r0[d] + r1[d] + r2[d];
        v[i] = t;
        lsum += t; lsq += t * t;
    }
    float total = blkSum<256>(lsum, red);
    float totsq = blkSum<256>(lsq, red);
    float mean = total * (1.f / D_);
    float var  = totsq * (1.f / D_) - mean * mean;
    float inv  = rsqrtf(var + 1e-5f);
#pragma unroll
    for (int i = 0; i < 3; i++) {
        int d = tid + i * 256;
        float o = (v[i] - mean) * inv * gs[d] + gb[d];
        long idx = (long)row * D_ + d;
        out[idx] = o;
        hsplit(o, oh[idx], ol[idx]);
    }
}

// ---------------- fp16-split tensor-core GEMM ---------------------------------
// C = epilogue(A @ B + bias). A=[M][K] (Ah+Al), B=[K][N] (Bh+Bl).
// Main term ah*bh -> f32 accumulator; corrections ah*bl + al*bh -> f16 accumulator.
// modes: 0 fp32 out (+resid); 1 gelu->f16 split; 2 qkv remap; 3 split-K partial
#define BM 128
#define BN 128
#define BKq 32
#define LDA_ 40
#define LDB_ 136
#define ASTG (BM * LDA_)
#define BSTG (BKq * LDB_)
#define STG_ELE (2 * ASTG + 2 * BSTG)
#define STG_BYTES (STG_ELE * 2)
#define GEMM_SMEM (2 * STG_BYTES)

__device__ __forceinline__ void load_stage(
    unsigned int sb,
    const __half* __restrict__ Ah, const __half* __restrict__ Al,
    const __half* __restrict__ Bh, const __half* __restrict__ Bl,
    int bRow, int bCol, int arow, int akc, int brow, int bcol,
    int k0, int N, int K)
{
    const __half* gah = Ah + (long)(bRow + arow) * K + k0 + akc;
    const __half* gal = Al + (long)(bRow + arow) * K + k0 + akc;
    cpasync16(sb + (arow * LDA_ + akc) * 2, gah);
    cpasync16(sb + ((arow + 64) * LDA_ + akc) * 2, gah + 64l * K);
    cpasync16(sb + ASTG * 2 + (arow * LDA_ + akc) * 2, gal);
    cpasync16(sb + ASTG * 2 + ((arow + 64) * LDA_ + akc) * 2, gal + 64l * K);
    const __half* gbh = Bh + (long)(k0 + brow) * N + bCol + bcol;
    const __half* gbl = Bl + (long)(k0 + brow) * N + bCol + bcol;
    cpasync16(sb + 2 * ASTG * 2 + (brow * LDB_ + bcol) * 2, gbh);
    cpasync16(sb + 2 * ASTG * 2 + ((brow + 16) * LDB_ + bcol) * 2, gbh + 16l * N);
    cpasync16(sb + (2 * ASTG + BSTG) * 2 + (brow * LDB_ + bcol) * 2, gbl);
    cpasync16(sb + (2 * ASTG + BSTG) * 2 + ((brow + 16) * LDB_ + bcol) * 2, gbl + 16l * N);
}

__global__ __launch_bounds__(256, 1)
void tgemm_kernel(const __half* __restrict__ Ah, const __half* __restrict__ Al,
                  const __half* __restrict__ Bh, const __half* __restrict__ Bl,
                  const float* __restrict__ bias, const float* __restrict__ resid,
                  float* __restrict__ C,
                  __half* __restrict__ Ch, __half* __restrict__ Cl,
                  int M, int N, int K, int Klen, int mode) {
    extern __shared__ __half smem[];
    const int tid  = threadIdx.x;
    const int lane = tid & 31;
    const int wid  = tid >> 5;
    const int wr   = wid >> 2;
    const int wc   = wid & 3;
    const int bRow = blockIdx.y * BM;
    const int bCol = blockIdx.x * BN;
    const int kz   = blockIdx.z;
    const int koff = kz * Klen;

    const int arow = tid >> 2;
    const int akc  = (tid & 3) * 8;
    const int brow = tid >> 4;
    const int bcol = (tid & 15) * 8;

    const unsigned int smem_u = (unsigned int)__cvta_generic_to_shared(smem);

    wmma::fragment<wmma::accumulator, 16, 16, 16, float> acc[4][2];
    wmma::fragment<wmma::accumulator, 16, 16, 16, __half> cacc[4][2];
#pragma unroll
    for (int i = 0; i < 4; i++)
#pragma unroll
        for (int j = 0; j < 2; j++) {
            wmma::fill_fragment(acc[i][j], 0.0f);
            wmma::fill_fragment(cacc[i][j], __float2half(0.0f));
        }

    const int nt = Klen / BKq;

    load_stage(smem_u, Ah, Al, Bh, Bl, bRow, bCol, arow, akc, brow, bcol, koff, N, K);
    cp_commit();

    for (int t = 0; t < nt; t++) {
        if (t + 1 < nt)
            load_stage(smem_u + ((t + 1) & 1) * STG_BYTES, Ah, Al, Bh, Bl,
                       bRow, bCol, arow, akc, brow, bcol, koff + (t + 1) * BKq, N, K);
        cp_commit();
        cp_wait1();
        __syncthreads();

        const __half* base = smem + (t & 1) * STG_ELE;
#pragma unroll
        for (int ks = 0; ks < BKq; ks += 16) {
            wmma::fragment<wmma::matrix_a, 16, 16, 16, __half, wmma::row_major> ah[4], al[4];
#pragma unroll
            for (int i = 0; i < 4; i++) {
                wmma::load_matrix_sync(ah[i], base + (wr * 64 + i * 16) * LDA_ + ks, LDA_);
                wmma::load_matrix_sync(al[i], base + ASTG + (wr * 64 + i * 16) * LDA_ + ks, LDA_);
            }
#pragma unroll
            for (int j = 0; j < 2; j++) {
                wmma::fragment<wmma::matrix_b, 16, 16, 16, __half, wmma::row_major> bh, bl;
                wmma::load_matrix_sync(bh, base + 2 * ASTG + ks * LDB_ + wc * 32 + j * 16, LDB_);
                wmma::load_matrix_sync(bl, base + 2 * ASTG + BSTG + ks * LDB_ + wc * 32 + j * 16, LDB_);
                // corrections in f16 accumulator (values ~2^-11 of main term)
#pragma unroll
                for (int i = 0; i < 4; i++)
                    wmma::mma_sync(cacc[i][j], ah[i], bl, cacc[i][j]);
#pragma unroll
                for (int i = 0; i < 4; i++)
                    wmma::mma_sync(cacc[i][j], al[i], bh, cacc[i][j]);
                // main term in f32 accumulator
#pragma unroll
                for (int i = 0; i < 4; i++)
                    wmma::mma_sync(acc[i][j], ah[i], bh, acc[i][j]);
            }
        }
        __syncthreads();
    }

    // epilogue: per-warp staging through (reused) smem; add f16 corr to f32 main
    float*  ws  = (float*)smem + wid * (16 * 36);
    __half* wsh = (__half*)((float*)smem + 8 * (16 * 36)) + wid * (16 * 36);
    const int gc = bCol + wc * 32 + lane;
#pragma unroll
    for (int mi = 0; mi < 4; mi++) {
        wmma::store_matrix_sync(ws,       acc[mi][0],  36, wmma::mem_row_major);
        wmma::store_matrix_sync(ws + 16,  acc[mi][1],  36, wmma::mem_row_major);
        wmma::store_matrix_sync(wsh,      cacc[mi][0], 36, wmma::mem_row_major);
        wmma::store_matrix_sync(wsh + 16, cacc[mi][1], 36, wmma::mem_row_major);
        __syncwarp();
        const int gr0 = bRow + wr * 64 + mi * 16;
#pragma unroll
        for (int r = 0; r < 16; r++) {
            float v = ws[r * 36 + lane] + __half2float(wsh[r * 36 + lane]);
            long idx = (long)(gr0 + r) * N + gc;
            if (mode == 0) {
                v += bias[gc];
                if (resid) v += resid[idx];
                C[idx] = v;
            } else if (mode == 1) {
                v += bias[gc];
                v = 0.5f * v * (1.0f + erff(v * 0.70710678118654752f));
                hsplit(v, Ch[idx], Cl[idx]);
            } else if (mode == 2) {  // packed qkv -> [t][s][e]
                v += bias[gc];
                int tq = gc / D_;
                C[(long)tq * S_ * D_ + (long)(gr0 + r) * D_ + (gc - tq * D_)] = v;
            } else {  // mode 3: split-K partial
                if (kz == 0) { v += bias[gc]; v += resid[idx]; }
                C[(long)kz * S_ * D_ + idx] = v;
            }
        }
        __syncwarp();
    }
}

// ---------------- fused banded flash attention --------------------------------
#define AT_LDQ 65
#define AT_LDK 68
#define ATTN_SMEM ((64 * AT_LDQ + 2 * 64 * AT_LDK) * 4)

__global__ __launch_bounds__(256)
void attn_fused_kernel(const float* __restrict__ qkv, const int* __restrict__ mask,
                       __half* __restrict__ ch, __half* __restrict__ cl) {
    extern __shared__ float asm_[];
    float* Qs  = asm_;
    float* KVs = asm_ + 64 * AT_LDQ;
    float* Ps  = KVs + 64 * AT_LDK;
    __shared__ int smask[64];

    const int q0  = blockIdx.x * 64;
    const int h   = blockIdx.y;
    const int tid = threadIdx.x;
    const int qg  = tid >> 4;
    const int tg  = tid & 15;

    const float* Qb = qkv;
    const float* Kb = qkv + (long)S_ * D_;
    const float* Vb = qkv + 2l * S_ * D_;

    for (int idx = tid; idx < 4096; idx += 256) {
        int r = idx >> 6, c = idx & 63;
        Qs[r * AT_LDQ + c] = Qb[(long)(q0 + r) * D_ + h * DH_ + c] * 0.125f;
    }

    float m[4], l[4], acc[4][4];
#pragma unroll
    for (int i = 0; i < 4; i++) {
        m[i] = -1e30f; l[i] = 0.f;
#pragma unroll
        for (int j = 0; j < 4; j++) acc[i][j] = 0.f;
    }

    for (int c9 = 0; c9 < 9; c9++) {
        const int jb = q0 - W_ + c9 * 64;
        __syncthreads();
        {
            int j  = tid & 63;
            int gj = jb + j;
            bool ok = (gj >= 0 && gj < S_);
            const float* kr = Kb + (long)gj * D_ + h * DH_;
            for (int d4 = (tid >> 6) * 4; d4 < 64; d4 += 16) {
                float4 k4 = ok ? *(const float4*)(kr + d4) : make_float4(0.f, 0.f, 0.f, 0.f);
                KVs[(d4 + 0) * AT_LDK + j] = k4.x;
                KVs[(d4 + 1) * AT_LDK + j] = k4.y;
                KVs[(d4 + 2) * AT_LDK + j] = k4.z;
                KVs[(d4 + 3) * AT_LDK + j] = k4.w;
            }
            if (tid < 64) smask[tid] = (jb + tid >= 0 && jb + tid < S_) ? mask[jb + tid] : 0;
        }
        __syncthreads();

        float s[4][4];
#pragma unroll
        for (int i = 0; i < 4; i++)
#pragma unroll
            for (int j = 0; j < 4; j++) s[i][j] = 0.f;
        for (int d = 0; d < 64; d++) {
            float4 kv = *(const float4*)&KVs[d * AT_LDK + tg * 4];
            float q0v = Qs[(qg * 4 + 0) * AT_LDQ + d];
            float q1v = Qs[(qg * 4 + 1) * AT_LDQ + d];
            float q2v = Qs[(qg * 4 + 2) * AT_LDQ + d];
            float q3v = Qs[(qg * 4 + 3) * AT_LDQ + d];
            s[0][0] = fmaf(q0v, kv.x, s[0][0]); s[0][1] = fmaf(q0v, kv.y, s[0][1]);
            s[0][2] = fmaf(q0v, kv.z, s[0][2]); s[0][3] = fmaf(q0v, kv.w, s[0][3]);
            s[1][0] = fmaf(q1v, kv.x, s[1][0]); s[1][1] = fmaf(q1v, kv.y, s[1][1]);
            s[1][2] = fmaf(q1v, kv.z, s[1][2]); s[1][3] = fmaf(q1v, kv.w, s[1][3]);
            s[2][0] = fmaf(q2v, kv.x, s[2][0]); s[2][1] = fmaf(q2v, kv.y, s[2][1]);
            s[2][2] = fmaf(q2v, kv.z, s[2][2]); s[2][3] = fmaf(q2v, kv.w, s[2][3]);
            s[3][0] = fmaf(q3v, kv.x, s[3][0]); s[3][1] = fmaf(q3v, kv.y, s[3][1]);
            s[3][2] = fmaf(q3v, kv.z, s[3][2]); s[3][3] = fmaf(q3v, kv.w, s[3][3]);
        }

#pragma unroll
        for (int i = 0; i < 4; i++) {
            int q = q0 + qg * 4 + i;
            float sv[4];
            float cm = -1e30f;
#pragma unroll
            for (int j = 0; j < 4; j++) {
                int gj = jb + tg * 4 + j;
                int rel = gj - q;
                bool ok = (rel >= -W_) && (rel <= W_) && smask[tg * 4 + j];
                sv[j] = ok ? s[i][j] : -1e9f;
                cm = fmaxf(cm, sv[j]);
            }
#pragma unroll
            for (int o = 1; o < 16; o <<= 1) cm = fmaxf(cm, __shfl_xor_sync(0xffffffffu, cm, o));
            float mn = fmaxf(m[i], cm);
            float alpha = __expf(m[i] - mn);
            float rs = 0.f;
#pragma unroll
            for (int j = 0; j < 4; j++) {
                float p = __expf(sv[j] - mn);
                Ps[(qg * 4 + i) * AT_LDK + tg * 4 + j] = p;
                rs += p;
            }
#pragma unroll
            for (int o = 1; o < 16; o <<= 1) rs += __shfl_xor_sync(0xffffffffu, rs, o);
            l[i] = l[i] * alpha + rs;
            m[i] = mn;
#pragma unroll
            for (int j = 0; j < 4; j++) acc[i][j] *= alpha;
        }
        __syncthreads();

        for (int idx = tid; idx < 1024; idx += 256) {
            int r = idx >> 4, c4 = (idx & 15) * 4;
            int gj = jb + r;
            float4 v4 = (gj >= 0 && gj < S_)
                        ? *(const float4*)(Vb + (long)gj * D_ + h * DH_ + c4)
                        : make_float4(0.f, 0.f, 0.f, 0.f);
            *(float4*)&KVs[r * AT_LDK + c4] = v4;
        }
        __syncthreads();

        for (int kl = 0; kl < 64; kl++) {
            float4 vv = *(const float4*)&KVs[kl * AT_LDK + tg * 4];
            float p0 = Ps[(qg * 4 + 0) * AT_LDK + kl];
            float p1 = Ps[(qg * 4 + 1) * AT_LDK + kl];
            float p2 = Ps[(qg * 4 + 2) * AT_LDK + kl];
            float p3 = Ps[(qg * 4 + 3) * AT_LDK + kl];
            acc[0][0] = fmaf(p0, vv.x, acc[0][0]); acc[0][1] = fmaf(p0, vv.y, acc[0][1]);
            acc[0][2] = fmaf(p0, vv.z, acc[0][2]); acc[0][3] = fmaf(p0, vv.w, acc[0][3]);
            acc[1][0] = fmaf(p1, vv.x, acc[1][0]); acc[1][1] = fmaf(p1, vv.y, acc[1][1]);
            acc[1][2] = fmaf(p1, vv.z, acc[1][2]); acc[1][3] = fmaf(p1, vv.w, acc[1][3]);
            acc[2][0] = fmaf(p2, vv.x, acc[2][0]); acc[2][1] = fmaf(p2, vv.y, acc[2][1]);
            acc[2][2] = fmaf(p2, vv.z, acc[2][2]); acc[2][3] = fmaf(p2, vv.w, acc[2][3]);
            acc[3][0] = fmaf(p3, vv.x, acc[3][0]); acc[3][1] = fmaf(p3, vv.y, acc[3][1]);
            acc[3][2] = fmaf(p3, vv.z, acc[3][2]); acc[3][3] = fmaf(p3, vv.w, acc[3][3]);
        }
    }

#pragma unroll
    for (int i = 0; i < 4; i++) {
        float inv = 1.0f / l[i];
#pragma unroll
        for (int j = 0; j < 4; j++) {
            long idx = (long)(q0 + qg * 4 + i) * D_ + h * DH_ + tg * 4 + j;
            hsplit(acc[i][j] * inv, ch[idx], cl[idx]);
        }
    }
}

// ---------------- pooled head --------------------------------------------------
__global__ void pool_kernel(const float* __restrict__ x, const float* __restrict__ Wp,
                            const float* __restrict__ bp, float* __restrict__ out) {
    __shared__ float x0[D_];
    int tid = threadIdx.x;
    for (int i = tid; i < D_; i += 128) x0[i] = x[i];
    __syncthreads();
    int e = blockIdx.x * 128 + tid;
    float acc = bp[e];
    for (int d = 0; d < D_; d++) acc = fmaf(x0[d], Wp[(long)d * D_ + e], acc);
    out[e] = tanhf(acc);
}

__global__ void copy_kernel(const float* __restrict__ in, float* __restrict__ out, int n) {
    int i = blockIdx.x * blockDim.x + threadIdx.x;
    if (i < n) out[i] = in[i];
}

// ---------------- launch --------------------------------------------------------
extern "C" void kernel_launch(void* const* d_in, const int* in_sizes, int n_in,
                              void* d_out, int out_size) {
    const int*   input_ids = (const int*)d_in[0];
    const int*   attn_mask = (const int*)d_in[1];
    const float* word_emb  = (const float*)d_in[2];
    const float* pos_emb   = (const float*)d_in[3];
    const float* type_emb  = (const float*)d_in[4];
    const float* emb_ln_s  = (const float*)d_in[5];
    const float* emb_ln_b  = (const float*)d_in[6];
    const float* Wqkv      = (const float*)d_in[7];
    const float* bqkv      = (const float*)d_in[8];
    const float* Wo        = (const float*)d_in[9];
    const float* bo        = (const float*)d_in[10];
    const float* ln1_s     = (const float*)d_in[11];
    const float* ln1_b     = (const float*)d_in[12];
    const float* W1        = (const float*)d_in[13];
    const float* b1        = (const float*)d_in[14];
    const float* W2        = (const float*)d_in[15];
    const float* b2        = (const float*)d_in[16];
    const float* ln2_s     = (const float*)d_in[17];
    const float* ln2_b     = (const float*)d_in[18];
    const float* pool_W    = (const float*)d_in[19];
    const float* pool_b    = (const float*)d_in[20];
    float* out = (float*)d_out;

    float *x, *qkv, *ys;
    int* pos;
    __half *xh, *xl, *ch, *cl, *hh, *hl;
    __half *wqh, *wql, *woh, *wol, *w1h, *w1l, *w2h, *w2l;
    cudaGetSymbolAddress((void**)&x, g_x);
    cudaGetSymbolAddress((void**)&qkv, g_qkv);
    cudaGetSymbolAddress((void**)&ys, g_ys);
    cudaGetSymbolAddress((void**)&pos, g_pos);
    cudaGetSymbolAddress((void**)&xh, g_xh); cudaGetSymbolAddress((void**)&xl, g_xl);
    cudaGetSymbolAddress((void**)&ch, g_ch); cudaGetSymbolAddress((void**)&cl, g_cl);
    cudaGetSymbolAddress((void**)&hh, g_hh); cudaGetSymbolAddress((void**)&hl, g_hl);
    cudaGetSymbolAddress((void**)&wqh, g_wqkv_h); cudaGetSymbolAddress((void**)&wql, g_wqkv_l);
    cudaGetSymbolAddress((void**)&woh, g_wo_h);   cudaGetSymbolAddress((void**)&wol, g_wo_l);
    cudaGetSymbolAddress((void**)&w1h, g_w1_h);   cudaGetSymbolAddress((void**)&w1l, g_w1_l);
    cudaGetSymbolAddress((void**)&w2h, g_w2_h);   cudaGetSymbolAddress((void**)&w2l, g_w2_l);

    cudaFuncSetAttribute(tgemm_kernel, cudaFuncAttributeMaxDynamicSharedMemorySize, GEMM_SMEM);
    cudaFuncSetAttribute(attn_fused_kernel, cudaFuncAttributeMaxDynamicSharedMemorySize, ATTN_SMEM);

    pos_kernel<<<1, 256>>>(attn_mask, pos);
    embed_ln_kernel<<<S_, 256>>>(input_ids, pos, word_emb, pos_emb, type_emb,
                                 emb_ln_s, emb_ln_b, x, xh, xl);
    split_plain_kernel<<<(L_ * D_ * F_) / 1024, 256>>>(W1, w1h, w1l);
    split_plain_kernel<<<(L_ * F_ * D_) / 1024, 256>>>(W2, w2h, w2l);
    split_qkv_kernel<<<(L_ * 3 * D_ * D_) / 1024, 256>>>(Wqkv, wqh, wql);

    for (int l = 0; l < L_; l++) {
        // fused QKV projection (N = 2304, qkv-remap epilogue)
        tgemm_kernel<<<dim3(QKV_N / BN, S_ / BM, 1), 256, GEMM_SMEM>>>(
            xh, xl, wqh + (long)l * D_ * QKV_N, wql + (long)l * D_ * QKV_N,
            bqkv + (long)l * QKV_N, nullptr, qkv, nullptr, nullptr,
            S_, QKV_N, D_, D_, 2);
        // fused banded flash attention
        attn_fused_kernel<<<dim3(S_ / 64, H_), 256, ATTN_SMEM>>>(qkv, attn_mask, ch, cl);
        if (l == 0)
            split_plain_kernel<<<(L_ * D_ * D_) / 1024, 256>>>(Wo, woh, wol);
        // output projection + residual (split-K=3) -> LN
        tgemm_kernel<<<dim3(D_ / BN, S_ / BM, 3), 256, GEMM_SMEM>>>(
            ch, cl, woh + (long)l * D_ * D_, wol + (long)l * D_ * D_,
            bo + (long)l * D_, x, ys, nullptr, nullptr, S_, D_, D_, D_ / 3, 3);
        ln3_kernel<<<S_, 256>>>(ys, ln1_s + (long)l * D_, ln1_b + (long)l * D_, x, xh, xl);
        // FFN: W1 (gelu -> f16 split), W2 (split-K=3, +resid) -> LN
        tgemm_kernel<<<dim3(F_ / BN, S_ / BM, 1), 256, GEMM_SMEM>>>(
            xh, xl, w1h + (long)l * D_ * F_, w1l + (long)l * D_ * F_,
            b1 + (long)l * F_, nullptr, nullptr, hh, hl, S_, F_, D_, D_, 1);
        tgemm_kernel<<<dim3(D_ / BN, S_ / BM, 3), 256, GEMM_SMEM>>>(
            hh, hl, w2h + (long)l * F_ * D_, w2l + (long)l * F_ * D_,
            b2 + (long)l * D_, x, ys, nullptr, nullptr, S_, D_, F_, F_ / 3, 3);
        ln3_kernel<<<S_, 256>>>(ys, ln2_s + (long)l * D_, ln2_b + (long)l * D_, x, xh, xl);
    }

    copy_kernel<<<(S_ * D_ + 255) / 256, 256>>>(x, out, S_ * D_);
    pool_kernel<<<D_ / 128, 128>>>(x, pool_W, pool_b, out + (long)S_ * D_);
}